// round 13
// baseline (speedup 1.0000x reference)
#include <cuda_runtime.h>
#include <cuda_fp16.h>
#include <math.h>
#include <stdint.h>

#define B_  32
#define T_  64
#define E_  512
#define H_  512
#define V_  10000
#define G_  2048          // 4*H
#define LNCTA 64          // LSTM CTAs
#define FNCTA 79          // FC worker CTAs

// ------------------------- device scratch (no allocs allowed) ---------------
__device__ __half g_hsb [T_ * B_ * H_];   // h history, fp16, b-major per t
__device__ float g_Gin [T_ * G_ * B_];    // [t][n][b]
__device__ unsigned g_flags[LNCTA * 32];  // 128B-strided per-CTA step flags

// ------------------------- helpers (baseline PTX, sm_80+) -------------------
__device__ __forceinline__ uint32_t smem_u32(const void* p) {
    uint32_t a;
    asm("{ .reg .u64 t; cvta.to.shared.u64 t, %1; cvt.u32.u64 %0, t; }"
        : "=r"(a) : "l"(p));
    return a;
}
__device__ __forceinline__ void ldsm4(uint32_t& r0, uint32_t& r1,
                                      uint32_t& r2, uint32_t& r3, uint32_t addr) {
    asm volatile("ldmatrix.sync.aligned.m8n8.x4.shared.b16 {%0,%1,%2,%3}, [%4];"
                 : "=r"(r0), "=r"(r1), "=r"(r2), "=r"(r3) : "r"(addr));
}
__device__ __forceinline__ void mma_f16(float* d, const uint32_t* a, const uint32_t* b) {
    asm volatile(
        "mma.sync.aligned.m16n8k16.row.col.f32.f16.f16.f32 "
        "{%0,%1,%2,%3}, {%4,%5,%6,%7}, {%8,%9}, {%0,%1,%2,%3};"
        : "+f"(d[0]), "+f"(d[1]), "+f"(d[2]), "+f"(d[3])
        : "r"(a[0]), "r"(a[1]), "r"(a[2]), "r"(a[3]), "r"(b[0]), "r"(b[1]));
}
__device__ __forceinline__ void cpa16(uint32_t saddr, const void* g) {
    asm volatile("cp.async.cg.shared.global [%0], [%1], 16;" :: "r"(saddr), "l"(g));
}
#define CP_COMMIT() asm volatile("cp.async.commit_group;" ::: "memory")
#define CP_WAIT(n)  asm volatile("cp.async.wait_group %0;" :: "n"(n) : "memory")

__device__ __forceinline__ unsigned ld_acq(const unsigned* p) {
    unsigned v;
    asm volatile("ld.acquire.gpu.u32 %0, [%1];" : "=r"(v) : "l"(p) : "memory");
    return v;
}
__device__ __forceinline__ void st_rel(unsigned* p, unsigned v) {
    asm volatile("st.release.gpu.u32 [%0], %1;" :: "l"(p), "r"(v) : "memory");
}
__device__ __forceinline__ void wait_flag(int q, unsigned target) {
    while (ld_acq(&g_flags[q * 32]) < target) { __nanosleep(16); }
}
__device__ __forceinline__ uint32_t h2u(__half2 h) {
    return *reinterpret_cast<uint32_t*>(&h);
}
__device__ __forceinline__ float sigmoidf_(float x) { return 1.f / (1.f + expf(-x)); }

__device__ __forceinline__ void split4(float4 v, uint2& hi, uint2& lo) {
    __half2 h0 = __floats2half2_rn(v.x, v.y);
    __half2 h1 = __floats2half2_rn(v.z, v.w);
    float2 r0 = __half22float2(h0), r1 = __half22float2(h1);
    __half2 l0 = __floats2half2_rn(v.x - r0.x, v.y - r0.y);
    __half2 l1 = __floats2half2_rn(v.z - r1.x, v.w - r1.y);
    hi = make_uint2(h2u(h0), h2u(h1));
    lo = make_uint2(h2u(l0), h2u(l1));
}

// ------------------------- fused Gin GEMM (prep + split + GEMM in one) ------
// Gin[t][n][b] = X @ W_ih^T + (b_ih + b_hh), fp16 2-pass (Xh + Xl) * W_fp16.
// A-tiles built directly from features/embed (fp32 -> in-register split);
// W_ih tile converted fp32 -> fp16 in-register. CTA(0,0) resets flags.
#define TS 40
#define GTILE_B (128 * TS * 2)              // 10240 bytes per tile
#define GOFF_AH 0
#define GOFF_AL (GOFF_AH + GTILE_B)
#define GOFF_BH (GOFF_AL + GTILE_B)
#define GOFF_BS (GOFF_BH + GTILE_B)         // bias: 128 floats
#define GOFF_TK (GOFF_BS + 512)             // toks: 128 ints
#define GSMEM   (GOFF_TK + 512)             // 31744

__global__ void __launch_bounds__(256, 2)
gin_fused(const float4* __restrict__ features4,
          const int*    __restrict__ captions,
          const float4* __restrict__ embed4,
          const float4* __restrict__ Wih4,
          const float*  __restrict__ b_ih,
          const float*  __restrict__ b_hh,
          float* __restrict__ C)
{
    extern __shared__ uint8_t dyn[];
    float* bias_s = (float*)(dyn + GOFF_BS);
    int*   toks   = (int*)  (dyn + GOFF_TK);

    const int tid  = threadIdx.x;
    const int wid  = tid >> 5;
    const int lane = tid & 31;
    const int n0   = blockIdx.x * 128;
    const int m0   = blockIdx.y * 128;

    // one CTA resets the fused-kernel flags (stream order guards usage)
    if (blockIdx.x == 0 && blockIdx.y == 0)
        for (int i = tid; i < LNCTA * 32; i += 256) g_flags[i] = 0;

    // toks + fused bias
    for (int i = tid; i < 128; i += 256) {
        int m = m0 + i, t = m >> 5, b = m & 31;
        int tok = 0;
        if (t > 0) {
            tok = captions[b * T_ + (t - 1)];
            tok = min(max(tok, 0), V_ - 1);
        }
        toks[i] = tok;
        int n = n0 + i;
        bias_s[i] = b_ih[n] + b_hh[n];
    }
    __syncthreads();

    const int mbase = (wid >> 1) * 32;
    const int nbase = (wid & 1) * 64;
    const int rowA  = mbase + (lane & 15);
    const int colA8 = (lane >> 4) << 3;
    const int g2    = lane >> 3;
    const int rowB  = nbase + ((g2 & 2) << 2) + (lane & 7);
    const int colB8 = (g2 & 1) << 3;

    const uint32_t sbase = smem_u32(dyn);
    const uint32_t aAh = sbase + GOFF_AH;
    const uint32_t aAl = sbase + GOFF_AL;
    const uint32_t aBh = sbase + GOFF_BH;

    float d[2][8][4];
#pragma unroll
    for (int i = 0; i < 2; i++)
#pragma unroll
        for (int j = 0; j < 8; j++)
#pragma unroll
            for (int q = 0; q < 4; q++) d[i][j][q] = 0.f;

    for (int kc = 0; kc < 16; ++kc) {
        if (kc) __syncthreads();            // protect previous mma's smem reads

        // ---- stage A: 128 rows x 32 floats from features/embed, split hi/lo ----
#pragma unroll
        for (int it = 0; it < 4; ++it) {
            int idx = tid + it * 256;       // 0..1023
            int row = idx >> 3, q = idx & 7;
            int m = m0 + row, t = m >> 5, b = m & 31;
            const float4* src = t ? (embed4 + (size_t)toks[row] * 128)
                                  : (features4 + b * 128);
            float4 v = src[kc * 8 + q];
            uint2 hi, lo;
            split4(v, hi, lo);
            *(uint2*)(dyn + GOFF_AH + (row * TS + q * 4) * 2) = hi;
            *(uint2*)(dyn + GOFF_AL + (row * TS + q * 4) * 2) = lo;
        }
        // ---- stage B: W_ih rows n0.., fp32 -> fp16 single ----
#pragma unroll
        for (int it = 0; it < 4; ++it) {
            int idx = tid + it * 256;
            int row = idx >> 3, q = idx & 7;
            float4 v = Wih4[(size_t)(n0 + row) * 128 + kc * 8 + q];
            __half2 h0 = __floats2half2_rn(v.x, v.y);
            __half2 h1 = __floats2half2_rn(v.z, v.w);
            *(uint2*)(dyn + GOFF_BH + (row * TS + q * 4) * 2)
                = make_uint2(h2u(h0), h2u(h1));
        }
        __syncthreads();

        // ---- mma: 2 k16 steps x 2 passes (Ah, Al) ----
#pragma unroll
        for (int ks = 0; ks < 2; ++ks) {
#pragma unroll
            for (int p = 0; p < 2; ++p) {
                const uint32_t baseA = p ? aAl : aAh;
                uint32_t a[2][4], b[8][2];
#pragma unroll
                for (int mb = 0; mb < 2; ++mb)
                    ldsm4(a[mb][0], a[mb][1], a[mb][2], a[mb][3],
                          baseA + ((rowA + mb * 16) * TS + ks * 16 + colA8) * 2);
#pragma unroll
                for (int nbp = 0; nbp < 4; ++nbp)
                    ldsm4(b[2*nbp][0], b[2*nbp][1], b[2*nbp+1][0], b[2*nbp+1][1],
                          aBh + ((rowB + nbp * 16) * TS + ks * 16 + colB8) * 2);
#pragma unroll
                for (int mb = 0; mb < 2; ++mb)
#pragma unroll
                    for (int nb = 0; nb < 8; ++nb)
                        mma_f16(d[mb][nb], a[mb], b[nb]);
            }
        }
    }

    // ---- epilogue: scatter to Gin[t][n][b] with bias ----
    const int gq = lane >> 2, tq = lane & 3;
#pragma unroll
    for (int mb = 0; mb < 2; ++mb) {
#pragma unroll
        for (int half = 0; half < 2; ++half) {
            int m = m0 + mbase + mb * 16 + gq + half * 8;
#pragma unroll
            for (int nb = 0; nb < 8; ++nb) {
                int nl = nbase + nb * 8 + tq * 2;
                int n  = n0 + nl;
                size_t base = (size_t)(m >> 5) * (G_ * B_) + (m & 31);
                C[base + (size_t)n * B_]       = d[mb][nb][half * 2 + 0] + bias_s[nl];
                C[base + (size_t)(n + 1) * B_] = d[mb][nb][half * 2 + 1] + bias_s[nl + 1];
            }
        }
    }
}

// ------------------------- fused persistent LSTM + FC (R11 structure) -------
#define LTS 520
#define L_WROW (32 * LTS * 2)               // 33280
#define OFF_WH 0
#define OFF_WL (OFF_WH + L_WROW)
#define OFF_AH (OFF_WL + L_WROW)
#define OFF_GT (OFF_AH + L_WROW)
#define LSMEM  (OFF_GT + 32 * 33 * 4)       // 104064
// FC layout
#define FTS 520
#define OFF_FB   0
#define FB_BYTES (128 * FTS * 2)            // 133120
#define OFF_FAH  (OFF_FB + FB_BYTES)
#define OFF_FBS  (OFF_FAH + 32 * FTS * 2)   // 166400
#define FSMEM    (OFF_FBS + 512)            // 166912
#define FUSED_SMEM (FSMEM > LSMEM ? FSMEM : LSMEM)

__global__ void __launch_bounds__(256, 1)
fused_lstm_fc(const float* __restrict__ Whh, const float* __restrict__ fcW,
              const float* __restrict__ fc_b, float* __restrict__ out)
{
    extern __shared__ uint8_t dyn[];
    const int tid  = threadIdx.x;
    const int bx   = blockIdx.x;
    const int w    = tid >> 5;
    const int lane = tid & 31;
    const uint32_t sb = smem_u32(dyn);
    const int srcq = tid & 63;

    if (bx < LNCTA) {
        // =================== LSTM role ===================
        float* gates = (float*)(dyn + OFF_GT);
        const uint32_t aWH = sb + OFF_WH;
        const uint32_t aWL = sb + OFF_WL;
        const uint32_t aAH = sb + OFF_AH;

        // load W_hh slice fp32 -> split hi/lo -> smem (one-time)
        {
            const float4* ws = (const float4*)Whh;
#pragma unroll 4
            for (int it = 0; it < 16; ++it) {
                int idx = tid + it * 256;
                int r = idx >> 7, qf = idx & 127;
                int gr = (r >> 3) * 512 + bx * 8 + (r & 7);
                float4 v = ws[(size_t)gr * 128 + qf];
                uint2 hi, lo;
                split4(v, hi, lo);
                *(uint2*)(dyn + OFF_WH + (r * LTS + qf * 4) * 2) = hi;
                *(uint2*)(dyn + OFF_WL + (r * LTS + qf * 4) * 2) = lo;
            }
        }

        const int mt = w & 1;
        const int nt = w >> 1;
        const int rowA  = mt * 16 + (lane & 15);
        const int colA8 = (lane >> 4) << 3;
        const int rowB  = nt * 8 + (lane & 7);
        const int colB8 = (lane >> 3) << 3;
        const int gq = lane >> 2, tq = lane & 3;

        float c_state = 0.f;
        const int jh = bx * 8 + w;
        __syncthreads();

        for (int t = 0; t < 64; ++t) {
            float gpre[4];
#pragma unroll
            for (int g = 0; g < 4; ++g)
                gpre[g] = __ldcg(&g_Gin[(size_t)t * (G_ * B_)
                                        + (size_t)(g * 512 + jh) * B_ + lane]);

            if (t > 0) {
                // ---- dataflow staging: wait on my producer, stage its slice ----
                wait_flag(srcq, (unsigned)t);
                const uint4* hh = (const uint4*)(g_hsb + (size_t)(t - 1) * B_ * H_);
#pragma unroll
                for (int it = 0; it < 8; ++it) {
                    int idx = tid + it * 256;          // = b*64 + srcq
                    int b = idx >> 6;
                    cpa16(aAH + (b * LTS + srcq * 8) * 2, hh + idx);
                }
                CP_COMMIT();
                CP_WAIT(0);
                __syncthreads();

                // ---- gates = h @ [W_hi; W_lo]^T : 2 chains x 32 k-steps ----
                float d0[4] = {0,0,0,0}, d1[4] = {0,0,0,0};
#pragma unroll
                for (int kb = 0; kb < 16; ++kb) {
                    uint32_t aH0[4], aH1[4], bH[4], bL[4];
                    ldsm4(aH0[0],aH0[1],aH0[2],aH0[3], aAH + (rowA*LTS + kb*32      + colA8)*2);
                    ldsm4(aH1[0],aH1[1],aH1[2],aH1[3], aAH + (rowA*LTS + kb*32 + 16 + colA8)*2);
                    ldsm4(bH[0],bH[1],bH[2],bH[3],     aWH + (rowB*LTS + kb*32 + colB8)*2);
                    ldsm4(bL[0],bL[1],bL[2],bL[3],     aWL + (rowB*LTS + kb*32 + colB8)*2);
                    mma_f16(d0, aH0, bH + 0);  mma_f16(d0, aH1, bH + 2);
                    mma_f16(d1, aH0, bL + 0);  mma_f16(d1, aH1, bL + 2);
                }
                {
                    int r0 = mt * 16 + gq;
                    int cc = nt * 8 + tq * 2;
                    gates[r0 * 33 + cc]           = d0[0] + d1[0];
                    gates[r0 * 33 + cc + 1]       = d0[1] + d1[1];
                    gates[(r0 + 8) * 33 + cc]     = d0[2] + d1[2];
                    gates[(r0 + 8) * 33 + cc + 1] = d0[3] + d1[3];
                }
            }
            __syncthreads();

            {
                const int b = lane;
                float gv[4];
#pragma unroll
                for (int g = 0; g < 4; ++g) {
                    float s = gpre[g];
                    if (t > 0) s += gates[b * 33 + g * 8 + w];
                    gv[g] = s;
                }
                float i_ = sigmoidf_(gv[0]);
                float f_ = sigmoidf_(gv[1]);
                float gg = tanhf(gv[2]);
                float o_ = sigmoidf_(gv[3]);
                c_state = f_ * c_state + i_ * gg;
                float h = o_ * tanhf(c_state);
                g_hsb[(size_t)t * B_ * H_ + b * 512 + jh] = __float2half(h);
            }

            __syncthreads();
            if (tid == 0) st_rel(&g_flags[bx * 32], (unsigned)(t + 1));
        }
    } else {
        // =================== FC worker role ===================
        const int j = bx - LNCTA;            // 0..78
        const int n0 = j * 128;
        float* bias_s = (float*)(dyn + OFF_FBS);
        const uint32_t aFB = sb + OFF_FB;
        const uint32_t aAH = sb + OFF_FAH;

        // load fc_W tile fp32 -> fp16 -> smem (one-time, hidden behind step 0)
        {
            const float4* fw = (const float4*)fcW;
#pragma unroll 8
            for (int it = 0; it < 64; ++it) {
                int idx = tid + it * 256;
                int r = idx >> 7, qf = idx & 127;
                int n = n0 + r;
                float4 v = (n < V_) ? fw[(size_t)n * 128 + qf]
                                    : make_float4(0.f, 0.f, 0.f, 0.f);
                __half2 h0 = __floats2half2_rn(v.x, v.y);
                __half2 h1 = __floats2half2_rn(v.z, v.w);
                *(uint2*)(dyn + OFF_FB + (r * FTS + qf * 4) * 2)
                    = make_uint2(h2u(h0), h2u(h1));
            }
        }
        for (int i = tid; i < 128; i += 256) {
            int n = n0 + i;
            bias_s[i] = (n < V_) ? fc_b[n] : 0.f;
        }
        __syncthreads();

        const int rowA  = lane & 15;
        const int colA8 = (lane >> 4) << 3;
        const int g2    = lane >> 3;
        const int rowB  = w * 16 + ((g2 & 2) << 2) + (lane & 7);
        const int colB8 = (g2 & 1) << 3;
        const int gq = lane >> 2, tq = lane & 3;

        for (int t = 0; t < 64; ++t) {
            wait_flag(srcq, (unsigned)(t + 1));
            {
                const uint4* hh = (const uint4*)(g_hsb + (size_t)t * B_ * H_);
#pragma unroll
                for (int it = 0; it < 8; ++it) {
                    int idx = tid + it * 256;
                    int b = idx >> 6;
                    cpa16(aAH + (b * FTS + srcq * 8) * 2, hh + idx);
                }
                CP_COMMIT();
                CP_WAIT(0);
                __syncthreads();
            }

            float d[2][2][4];
#pragma unroll
            for (int i = 0; i < 2; i++)
#pragma unroll
                for (int jn = 0; jn < 2; jn++)
#pragma unroll
                    for (int q = 0; q < 4; q++) d[i][jn][q] = 0.f;
#pragma unroll
            for (int kb = 0; kb < 32; ++kb) {
                uint32_t aH[2][4], b[2][2];
                ldsm4(aH[0][0],aH[0][1],aH[0][2],aH[0][3], aAH + ((rowA     )*FTS + kb*16 + colA8)*2);
                ldsm4(aH[1][0],aH[1][1],aH[1][2],aH[1][3], aAH + ((rowA + 16)*FTS + kb*16 + colA8)*2);
                ldsm4(b[0][0], b[0][1], b[1][0], b[1][1],  aFB + (rowB*FTS + kb*16 + colB8)*2);
#pragma unroll
                for (int mb = 0; mb < 2; ++mb)
#pragma unroll
                    for (int nb = 0; nb < 2; ++nb)
                        mma_f16(d[mb][nb], aH[mb], b[nb]);
            }

#pragma unroll
            for (int mb = 0; mb < 2; ++mb) {
#pragma unroll
                for (int half = 0; half < 2; ++half) {
                    int b = mb * 16 + gq + half * 8;
                    float* crow = out + (size_t)b * (T_ * V_) + (size_t)t * V_;
#pragma unroll
                    for (int nb = 0; nb < 2; ++nb) {
                        int nl = w * 16 + nb * 8 + tq * 2;
                        int n  = n0 + nl;
                        if (n < V_) {
                            float2 o;
                            o.x = d[mb][nb][half * 2 + 0] + bias_s[nl];
                            o.y = d[mb][nb][half * 2 + 1] + bias_s[nl + 1];
                            *(float2*)&crow[n] = o;
                        }
                    }
                }
            }
            __syncthreads();
        }
    }
}

// ------------------------- launch ------------------------------------------
extern "C" void kernel_launch(void* const* d_in, const int* in_sizes, int n_in,
                              void* d_out, int out_size)
{
    const float* features = (const float*)d_in[0];
    const int*   captions = (const int*)d_in[1];
    // d_in[2] = forward_approach (unused)
    const float* embed = (const float*)d_in[3];
    const float* W_ih  = (const float*)d_in[4];
    const float* W_hh  = (const float*)d_in[5];
    const float* b_ih  = (const float*)d_in[6];
    const float* b_hh  = (const float*)d_in[7];
    const float* fc_W  = (const float*)d_in[8];
    const float* fc_b  = (const float*)d_in[9];
    float* out = (float*)d_out;

    float* pGin;
    cudaGetSymbolAddress((void**)&pGin, g_Gin);

    cudaFuncSetAttribute(gin_fused, cudaFuncAttributeMaxDynamicSharedMemorySize, GSMEM);
    cudaFuncSetAttribute(fused_lstm_fc, cudaFuncAttributeMaxDynamicSharedMemorySize, FUSED_SMEM);

    // 1) Gin[t][n][b] = X @ W_ih^T + (b_ih + b_hh)
    //    (X built from features/embed inline; W_ih converted inline; flags reset)
    gin_fused<<<dim3(G_ / 128, (T_ * B_) / 128), 256, GSMEM>>>(
        (const float4*)features, captions, (const float4*)embed,
        (const float4*)W_ih, b_ih, b_hh, pGin);

    // 2) fused persistent LSTM + FC (R11 structure)
    fused_lstm_fc<<<LNCTA + FNCTA, 256, FUSED_SMEM>>>(W_hh, fc_W, fc_b, out);
}

// round 14
// speedup vs baseline: 1.1484x; 1.1484x over previous
#include <cuda_runtime.h>
#include <cuda_fp16.h>
#include <math.h>
#include <stdint.h>

#define B_  32
#define T_  64
#define E_  512
#define H_  512
#define V_  10000
#define G_  2048          // 4*H
#define LNCTA 64          // LSTM CTAs
#define FNCTA 79          // FC worker CTAs

// ------------------------- device scratch (no allocs allowed) ---------------
__device__ __half g_Xh  [T_ * B_ * E_];
__device__ __half g_Xl  [T_ * B_ * E_];
__device__ __half g_Wih_h[G_ * E_];
__device__ __half g_hsb [T_ * B_ * H_];   // h history, fp16, b-major per t
__device__ float g_Gin [T_ * G_ * B_];    // [t][n][b]
__device__ float g_biasg[G_];
__device__ unsigned g_flags[LNCTA * 32];  // 128B-strided per-CTA step flags

// ------------------------- helpers (baseline PTX, sm_80+) -------------------
__device__ __forceinline__ uint32_t smem_u32(const void* p) {
    uint32_t a;
    asm("{ .reg .u64 t; cvta.to.shared.u64 t, %1; cvt.u32.u64 %0, t; }"
        : "=r"(a) : "l"(p));
    return a;
}
__device__ __forceinline__ void ldsm4(uint32_t& r0, uint32_t& r1,
                                      uint32_t& r2, uint32_t& r3, uint32_t addr) {
    asm volatile("ldmatrix.sync.aligned.m8n8.x4.shared.b16 {%0,%1,%2,%3}, [%4];"
                 : "=r"(r0), "=r"(r1), "=r"(r2), "=r"(r3) : "r"(addr));
}
__device__ __forceinline__ void mma_f16(float* d, const uint32_t* a, const uint32_t* b) {
    asm volatile(
        "mma.sync.aligned.m16n8k16.row.col.f32.f16.f16.f32 "
        "{%0,%1,%2,%3}, {%4,%5,%6,%7}, {%8,%9}, {%0,%1,%2,%3};"
        : "+f"(d[0]), "+f"(d[1]), "+f"(d[2]), "+f"(d[3])
        : "r"(a[0]), "r"(a[1]), "r"(a[2]), "r"(a[3]), "r"(b[0]), "r"(b[1]));
}
__device__ __forceinline__ void cpa16(uint32_t saddr, const void* g) {
    asm volatile("cp.async.cg.shared.global [%0], [%1], 16;" :: "r"(saddr), "l"(g));
}
#define CP_COMMIT() asm volatile("cp.async.commit_group;" ::: "memory")
#define CP_WAIT(n)  asm volatile("cp.async.wait_group %0;" :: "n"(n) : "memory")

__device__ __forceinline__ unsigned ld_acq(const unsigned* p) {
    unsigned v;
    asm volatile("ld.acquire.gpu.u32 %0, [%1];" : "=r"(v) : "l"(p) : "memory");
    return v;
}
__device__ __forceinline__ void st_rel(unsigned* p, unsigned v) {
    asm volatile("st.release.gpu.u32 [%0], %1;" :: "l"(p), "r"(v) : "memory");
}
__device__ __forceinline__ void wait_flag(int q, unsigned target) {
    while (ld_acq(&g_flags[q * 32]) < target) { __nanosleep(16); }
}
__device__ __forceinline__ uint32_t h2u(__half2 h) {
    return *reinterpret_cast<uint32_t*>(&h);
}
__device__ __forceinline__ float sigmoidf_(float x) { return 1.f / (1.f + expf(-x)); }

__device__ __forceinline__ void split4(float4 v, uint2& hi, uint2& lo) {
    __half2 h0 = __floats2half2_rn(v.x, v.y);
    __half2 h1 = __floats2half2_rn(v.z, v.w);
    float2 r0 = __half22float2(h0), r1 = __half22float2(h1);
    __half2 l0 = __floats2half2_rn(v.x - r0.x, v.y - r0.y);
    __half2 l1 = __floats2half2_rn(v.z - r1.x, v.w - r1.y);
    hi = make_uint2(h2u(h0), h2u(h1));
    lo = make_uint2(h2u(l0), h2u(l1));
}

// ------------------------- prep: split-X (vectorized) + bias + flag reset ---
__global__ void prep_kernel(const float4* __restrict__ features4,
                            const int* __restrict__ captions,
                            const float4* __restrict__ embed4,
                            const float4* __restrict__ b_ih4,
                            const float4* __restrict__ b_hh4)
{
    int i = blockIdx.x * blockDim.x + threadIdx.x;   // over T*B*E/4 = 262,144
    int e4 = i & 127;
    int b  = (i >> 7) & (B_ - 1);
    int t  = i >> 12;
    float4 v;
    if (t == 0) {
        v = features4[b * 128 + e4];
    } else {
        int tok = captions[b * T_ + (t - 1)];
        tok = min(max(tok, 0), V_ - 1);
        v = embed4[(size_t)tok * 128 + e4];
    }
    uint2 hi, lo;
    split4(v, hi, lo);
    ((uint2*)g_Xh)[i] = hi;
    ((uint2*)g_Xl)[i] = lo;
    if (i < G_ / 4) {
        float4 a = b_ih4[i], c = b_hh4[i];
        ((float4*)g_biasg)[i] = make_float4(a.x + c.x, a.y + c.y, a.z + c.z, a.w + c.w);
    }
    if (i < LNCTA * 32) g_flags[i] = 0;
}

// ------------------------- W_ih hi-only split --------------------------------
__global__ void split_hi_kernel(const float4* __restrict__ src,
                                uint2* __restrict__ hi, int n4)
{
    int i = blockIdx.x * 256 + threadIdx.x;
    if (i >= n4) return;
    float4 v = src[i];
    __half2 h0 = __floats2half2_rn(v.x, v.y);
    __half2 h1 = __floats2half2_rn(v.z, v.w);
    hi[i] = make_uint2(h2u(h0), h2u(h1));
}

// ------------------------- Gin GEMM (fp16 2-pass, cp.async pipelined) -------
#define TS 40
#define TILE_B (128 * TS * 2)

__global__ void __launch_bounds__(256, 2)
gin_gemm(const __half* __restrict__ Ah, const __half* __restrict__ Al,
         const __half* __restrict__ Bh,
         const float* __restrict__ bias, float* __restrict__ C)
{
    constexpr int NT = 3;
    constexpr int STAGE = NT * TILE_B;

    extern __shared__ uint8_t dyn[];
    float* bias_s = (float*)(dyn + 2 * STAGE);

    const int tid  = threadIdx.x;
    const int wid  = tid >> 5;
    const int lane = tid & 31;
    const int n0   = blockIdx.x * 128;
    const int m0   = blockIdx.y * 128;

    const int mbase = (wid >> 1) * 32;
    const int nbase = (wid & 1) * 64;

    for (int i = tid; i < 128; i += 256) bias_s[i] = bias[n0 + i];

    const int rowA  = mbase + (lane & 15);
    const int colA8 = (lane >> 4) << 3;
    const int g2    = lane >> 3;
    const int rowB  = nbase + ((g2 & 2) << 2) + (lane & 7);
    const int colB8 = (g2 & 1) << 3;

    const uint32_t sbase = smem_u32(dyn);

    const uint4* gsrc[3] = {
        (const uint4*)(Ah + (size_t)m0 * 512), (const uint4*)(Al + (size_t)m0 * 512),
        (const uint4*)(Bh + (size_t)n0 * 512) };

    float d[2][8][4];
#pragma unroll
    for (int i = 0; i < 2; i++)
#pragma unroll
        for (int j = 0; j < 8; j++)
#pragma unroll
            for (int q = 0; q < 4; q++) d[i][j][q] = 0.f;

#pragma unroll
    for (int it = 0; it < 6; ++it) {
        int s = tid + it * 256, mat = s >> 9, rem = s & 511, row = rem >> 2, q = rem & 3;
        cpa16(sbase + mat * TILE_B + (row * TS + q * 8) * 2,
              gsrc[mat] + (size_t)row * 64 + q);
    }
    CP_COMMIT();

    for (int kc = 0; kc < 16; ++kc) {
        const int cur = kc & 1;
        if (kc < 15) {
            const uint32_t st = sbase + (cur ^ 1) * STAGE;
#pragma unroll
            for (int it = 0; it < 6; ++it) {
                int s = tid + it * 256, mat = s >> 9, rem = s & 511, row = rem >> 2, q = rem & 3;
                cpa16(st + mat * TILE_B + (row * TS + q * 8) * 2,
                      gsrc[mat] + (size_t)row * 64 + (kc + 1) * 4 + q);
            }
            CP_COMMIT();
            CP_WAIT(1);
        } else {
            CP_WAIT(0);
        }
        __syncthreads();

        const uint32_t aAh = sbase + cur * STAGE;
        const uint32_t aAl = aAh + TILE_B;
        const uint32_t aBh = aAl + TILE_B;
#pragma unroll
        for (int ks = 0; ks < 2; ++ks) {
#pragma unroll
            for (int p = 0; p < 2; ++p) {
                const uint32_t baseA = p ? aAl : aAh;
                uint32_t a[2][4], b[8][2];
#pragma unroll
                for (int mb = 0; mb < 2; ++mb)
                    ldsm4(a[mb][0], a[mb][1], a[mb][2], a[mb][3],
                          baseA + ((rowA + mb * 16) * TS + ks * 16 + colA8) * 2);
#pragma unroll
                for (int nbp = 0; nbp < 4; ++nbp)
                    ldsm4(b[2*nbp][0], b[2*nbp][1], b[2*nbp+1][0], b[2*nbp+1][1],
                          aBh + ((rowB + nbp * 16) * TS + ks * 16 + colB8) * 2);
#pragma unroll
                for (int mb = 0; mb < 2; ++mb)
#pragma unroll
                    for (int nb = 0; nb < 8; ++nb)
                        mma_f16(d[mb][nb], a[mb], b[nb]);
            }
        }
        __syncthreads();
    }

    const int gq = lane >> 2, tq = lane & 3;
#pragma unroll
    for (int mb = 0; mb < 2; ++mb) {
#pragma unroll
        for (int half = 0; half < 2; ++half) {
            int m = m0 + mbase + mb * 16 + gq + half * 8;
#pragma unroll
            for (int nb = 0; nb < 8; ++nb) {
                int nl = nbase + nb * 8 + tq * 2;
                int n  = n0 + nl;
                size_t base = (size_t)(m >> 5) * (G_ * B_) + (m & 31);
                C[base + (size_t)n * B_]       = d[mb][nb][half * 2 + 0] + bias_s[nl];
                C[base + (size_t)(n + 1) * B_] = d[mb][nb][half * 2 + 1] + bias_s[nl + 1];
            }
        }
    }
}

// ------------------------- fused persistent LSTM + FC -----------------------
// R11 structure; ONE change: gate mma is 1-pass (W_hh rounded to fp16, no
// low-half) — halves the LSTM per-step tensor work and the W smem footprint.
#define LTS 520
#define L_WROW (32 * LTS * 2)               // 33280
#define OFF_WH 0
#define OFF_AH (OFF_WH + L_WROW)
#define OFF_GT (OFF_AH + L_WROW)
#define LSMEM  (OFF_GT + 32 * 33 * 4)       // 70784
// FC layout
#define FTS 520
#define OFF_FB   0
#define FB_BYTES (128 * FTS * 2)            // 133120
#define OFF_FAH  (OFF_FB + FB_BYTES)
#define OFF_FBS  (OFF_FAH + 32 * FTS * 2)   // 166400
#define FSMEM    (OFF_FBS + 512)            // 166912
#define FUSED_SMEM (FSMEM > LSMEM ? FSMEM : LSMEM)

__global__ void __launch_bounds__(256, 1)
fused_lstm_fc(const float* __restrict__ Whh, const float* __restrict__ fcW,
              const float* __restrict__ fc_b, float* __restrict__ out)
{
    extern __shared__ uint8_t dyn[];
    const int tid  = threadIdx.x;
    const int bx   = blockIdx.x;
    const int w    = tid >> 5;
    const int lane = tid & 31;
    const uint32_t sb = smem_u32(dyn);
    const int srcq = tid & 63;

    if (bx < LNCTA) {
        // =================== LSTM role ===================
        float* gates = (float*)(dyn + OFF_GT);
        const uint32_t aWH = sb + OFF_WH;
        const uint32_t aAH = sb + OFF_AH;

        // load W_hh slice fp32 -> fp16 (round) -> smem (one-time)
        {
            const float4* ws = (const float4*)Whh;
#pragma unroll 4
            for (int it = 0; it < 16; ++it) {
                int idx = tid + it * 256;
                int r = idx >> 7, qf = idx & 127;
                int gr = (r >> 3) * 512 + bx * 8 + (r & 7);
                float4 v = ws[(size_t)gr * 128 + qf];
                __half2 h0 = __floats2half2_rn(v.x, v.y);
                __half2 h1 = __floats2half2_rn(v.z, v.w);
                *(uint2*)(dyn + OFF_WH + (r * LTS + qf * 4) * 2)
                    = make_uint2(h2u(h0), h2u(h1));
            }
        }

        const int mt = w & 1;
        const int nt = w >> 1;
        const int rowA  = mt * 16 + (lane & 15);
        const int colA8 = (lane >> 4) << 3;
        const int rowB  = nt * 8 + (lane & 7);
        const int colB8 = (lane >> 3) << 3;
        const int gq = lane >> 2, tq = lane & 3;

        float c_state = 0.f;
        const int jh = bx * 8 + w;
        __syncthreads();

        for (int t = 0; t < 64; ++t) {
            float gpre[4];
#pragma unroll
            for (int g = 0; g < 4; ++g)
                gpre[g] = __ldcg(&g_Gin[(size_t)t * (G_ * B_)
                                        + (size_t)(g * 512 + jh) * B_ + lane]);

            if (t > 0) {
                // ---- dataflow staging: wait on my producer, stage its slice ----
                wait_flag(srcq, (unsigned)t);
                const uint4* hh = (const uint4*)(g_hsb + (size_t)(t - 1) * B_ * H_);
#pragma unroll
                for (int it = 0; it < 8; ++it) {
                    int idx = tid + it * 256;          // = b*64 + srcq
                    int b = idx >> 6;
                    cpa16(aAH + (b * LTS + srcq * 8) * 2, hh + idx);
                }
                CP_COMMIT();
                CP_WAIT(0);
                __syncthreads();

                // ---- gates = h @ W_hi^T : 1 pass x 32 k-steps ----
                float d0[4] = {0, 0, 0, 0};
#pragma unroll
                for (int kb = 0; kb < 16; ++kb) {
                    uint32_t aH0[4], aH1[4], bH[4];
                    ldsm4(aH0[0],aH0[1],aH0[2],aH0[3], aAH + (rowA*LTS + kb*32      + colA8)*2);
                    ldsm4(aH1[0],aH1[1],aH1[2],aH1[3], aAH + (rowA*LTS + kb*32 + 16 + colA8)*2);
                    ldsm4(bH[0],bH[1],bH[2],bH[3],     aWH + (rowB*LTS + kb*32 + colB8)*2);
                    mma_f16(d0, aH0, bH + 0);
                    mma_f16(d0, aH1, bH + 2);
                }
                {
                    int r0 = mt * 16 + gq;
                    int cc = nt * 8 + tq * 2;
                    gates[r0 * 33 + cc]           = d0[0];
                    gates[r0 * 33 + cc + 1]       = d0[1];
                    gates[(r0 + 8) * 33 + cc]     = d0[2];
                    gates[(r0 + 8) * 33 + cc + 1] = d0[3];
                }
            }
            __syncthreads();

            {
                const int b = lane;
                float gv[4];
#pragma unroll
                for (int g = 0; g < 4; ++g) {
                    float s = gpre[g];
                    if (t > 0) s += gates[b * 33 + g * 8 + w];
                    gv[g] = s;
                }
                float i_ = sigmoidf_(gv[0]);
                float f_ = sigmoidf_(gv[1]);
                float gg = tanhf(gv[2]);
                float o_ = sigmoidf_(gv[3]);
                c_state = f_ * c_state + i_ * gg;
                float h = o_ * tanhf(c_state);
                g_hsb[(size_t)t * B_ * H_ + b * 512 + jh] = __float2half(h);
            }

            __syncthreads();
            if (tid == 0) st_rel(&g_flags[bx * 32], (unsigned)(t + 1));
        }
    } else {
        // =================== FC worker role ===================
        const int j = bx - LNCTA;            // 0..78
        const int n0 = j * 128;
        float* bias_s = (float*)(dyn + OFF_FBS);
        const uint32_t aFB = sb + OFF_FB;
        const uint32_t aAH = sb + OFF_FAH;

        // load fc_W tile fp32 -> fp16 -> smem (one-time, hidden behind step 0)
        {
            const float4* fw = (const float4*)fcW;
#pragma unroll 8
            for (int it = 0; it < 64; ++it) {
                int idx = tid + it * 256;
                int r = idx >> 7, qf = idx & 127;
                int n = n0 + r;
                float4 v = (n < V_) ? fw[(size_t)n * 128 + qf]
                                    : make_float4(0.f, 0.f, 0.f, 0.f);
                __half2 h0 = __floats2half2_rn(v.x, v.y);
                __half2 h1 = __floats2half2_rn(v.z, v.w);
                *(uint2*)(dyn + OFF_FB + (r * FTS + qf * 4) * 2)
                    = make_uint2(h2u(h0), h2u(h1));
            }
        }
        for (int i = tid; i < 128; i += 256) {
            int n = n0 + i;
            bias_s[i] = (n < V_) ? fc_b[n] : 0.f;
        }
        __syncthreads();

        const int rowA  = lane & 15;
        const int colA8 = (lane >> 4) << 3;
        const int g2    = lane >> 3;
        const int rowB  = w * 16 + ((g2 & 2) << 2) + (lane & 7);
        const int colB8 = (g2 & 1) << 3;
        const int gq = lane >> 2, tq = lane & 3;

        for (int t = 0; t < 64; ++t) {
            wait_flag(srcq, (unsigned)(t + 1));
            {
                const uint4* hh = (const uint4*)(g_hsb + (size_t)t * B_ * H_);
#pragma unroll
                for (int it = 0; it < 8; ++it) {
                    int idx = tid + it * 256;
                    int b = idx >> 6;
                    cpa16(aAH + (b * FTS + srcq * 8) * 2, hh + idx);
                }
                CP_COMMIT();
                CP_WAIT(0);
                __syncthreads();
            }

            float d[2][2][4];
#pragma unroll
            for (int i = 0; i < 2; i++)
#pragma unroll
                for (int jn = 0; jn < 2; jn++)
#pragma unroll
                    for (int q = 0; q < 4; q++) d[i][jn][q] = 0.f;
#pragma unroll
            for (int kb = 0; kb < 32; ++kb) {
                uint32_t aH[2][4], b[2][2];
                ldsm4(aH[0][0],aH[0][1],aH[0][2],aH[0][3], aAH + ((rowA     )*FTS + kb*16 + colA8)*2);
                ldsm4(aH[1][0],aH[1][1],aH[1][2],aH[1][3], aAH + ((rowA + 16)*FTS + kb*16 + colA8)*2);
                ldsm4(b[0][0], b[0][1], b[1][0], b[1][1],  aFB + (rowB*FTS + kb*16 + colB8)*2);
#pragma unroll
                for (int mb = 0; mb < 2; ++mb)
#pragma unroll
                    for (int nb = 0; nb < 2; ++nb)
                        mma_f16(d[mb][nb], aH[mb], b[nb]);
            }

#pragma unroll
            for (int mb = 0; mb < 2; ++mb) {
#pragma unroll
                for (int half = 0; half < 2; ++half) {
                    int b = mb * 16 + gq + half * 8;
                    float* crow = out + (size_t)b * (T_ * V_) + (size_t)t * V_;
#pragma unroll
                    for (int nb = 0; nb < 2; ++nb) {
                        int nl = w * 16 + nb * 8 + tq * 2;
                        int n  = n0 + nl;
                        if (n < V_) {
                            float2 o;
                            o.x = d[mb][nb][half * 2 + 0] + bias_s[nl];
                            o.y = d[mb][nb][half * 2 + 1] + bias_s[nl + 1];
                            *(float2*)&crow[n] = o;
                        }
                    }
                }
            }
            __syncthreads();
        }
    }
}

// ------------------------- launch ------------------------------------------
extern "C" void kernel_launch(void* const* d_in, const int* in_sizes, int n_in,
                              void* d_out, int out_size)
{
    const float* features = (const float*)d_in[0];
    const int*   captions = (const int*)d_in[1];
    // d_in[2] = forward_approach (unused)
    const float* embed = (const float*)d_in[3];
    const float* W_ih  = (const float*)d_in[4];
    const float* W_hh  = (const float*)d_in[5];
    const float* b_ih  = (const float*)d_in[6];
    const float* b_hh  = (const float*)d_in[7];
    const float* fc_W  = (const float*)d_in[8];
    const float* fc_b  = (const float*)d_in[9];
    float* out = (float*)d_out;

    float *pGin, *pbias;
    __half *pXh, *pXl, *pWih_h;
    cudaGetSymbolAddress((void**)&pGin,   g_Gin);
    cudaGetSymbolAddress((void**)&pbias,  g_biasg);
    cudaGetSymbolAddress((void**)&pXh,    g_Xh);
    cudaGetSymbolAddress((void**)&pXl,    g_Xl);
    cudaGetSymbolAddress((void**)&pWih_h, g_Wih_h);

    const int SMEM_G2 = 2 * 3 * TILE_B + 512;    // 61952
    cudaFuncSetAttribute(gin_gemm, cudaFuncAttributeMaxDynamicSharedMemorySize, SMEM_G2);
    cudaFuncSetAttribute(fused_lstm_fc, cudaFuncAttributeMaxDynamicSharedMemorySize, FUSED_SMEM);

    // 1) build split X + fused bias + reset barrier flags
    prep_kernel<<<(T_ * B_ * E_ / 4) / 256, 256>>>(
        (const float4*)features, captions, (const float4*)embed,
        (const float4*)b_ih, (const float4*)b_hh);

    // 2) W_ih hi-only split
    split_hi_kernel<<<(G_ * E_ / 4 + 255) / 256, 256>>>(
        (const float4*)W_ih, (uint2*)pWih_h, G_ * E_ / 4);

    // 3) Gin[t][n][b] = X @ W_ih^T + (b_ih + b_hh)   (fp16 2-pass)
    gin_gemm<<<dim3(G_ / 128, (T_ * B_) / 128), 256, SMEM_G2>>>(
        pXh, pXl, pWih_h, pbias, pGin);

    // 4) fused persistent LSTM + FC (1-pass gate mma)
    fused_lstm_fc<<<LNCTA + FNCTA, 256, FUSED_SMEM>>>(W_hh, fc_W, fc_b, out);
}

// round 15
// speedup vs baseline: 1.1585x; 1.0088x over previous
#include <cuda_runtime.h>
#include <cuda_fp16.h>
#include <math.h>
#include <stdint.h>

#define B_  32
#define T_  64
#define E_  512
#define H_  512
#define V_  10000
#define G_  2048          // 4*H
#define LNCTA 64          // LSTM CTAs
#define FNCTA 79          // FC worker CTAs

// ------------------------- device scratch (no allocs allowed) ---------------
__device__ __half g_Xh  [T_ * B_ * E_];
__device__ __half g_Wih_h[G_ * E_];
__device__ __half g_hsb [T_ * B_ * H_];   // h history, fp16, b-major per t
__device__ float g_Gin [T_ * G_ * B_];    // [t][n][b]
__device__ float g_biasg[G_];
__device__ unsigned g_flags[LNCTA * 32];  // 128B-strided per-CTA step flags

// ------------------------- helpers (baseline PTX, sm_80+) -------------------
__device__ __forceinline__ uint32_t smem_u32(const void* p) {
    uint32_t a;
    asm("{ .reg .u64 t; cvta.to.shared.u64 t, %1; cvt.u32.u64 %0, t; }"
        : "=r"(a) : "l"(p));
    return a;
}
__device__ __forceinline__ void ldsm4(uint32_t& r0, uint32_t& r1,
                                      uint32_t& r2, uint32_t& r3, uint32_t addr) {
    asm volatile("ldmatrix.sync.aligned.m8n8.x4.shared.b16 {%0,%1,%2,%3}, [%4];"
                 : "=r"(r0), "=r"(r1), "=r"(r2), "=r"(r3) : "r"(addr));
}
__device__ __forceinline__ void mma_f16(float* d, const uint32_t* a, const uint32_t* b) {
    asm volatile(
        "mma.sync.aligned.m16n8k16.row.col.f32.f16.f16.f32 "
        "{%0,%1,%2,%3}, {%4,%5,%6,%7}, {%8,%9}, {%0,%1,%2,%3};"
        : "+f"(d[0]), "+f"(d[1]), "+f"(d[2]), "+f"(d[3])
        : "r"(a[0]), "r"(a[1]), "r"(a[2]), "r"(a[3]), "r"(b[0]), "r"(b[1]));
}
__device__ __forceinline__ void cpa16(uint32_t saddr, const void* g) {
    asm volatile("cp.async.cg.shared.global [%0], [%1], 16;" :: "r"(saddr), "l"(g));
}
#define CP_COMMIT() asm volatile("cp.async.commit_group;" ::: "memory")
#define CP_WAIT(n)  asm volatile("cp.async.wait_group %0;" :: "n"(n) : "memory")

__device__ __forceinline__ unsigned ld_acq(const unsigned* p) {
    unsigned v;
    asm volatile("ld.acquire.gpu.u32 %0, [%1];" : "=r"(v) : "l"(p) : "memory");
    return v;
}
__device__ __forceinline__ void st_rel(unsigned* p, unsigned v) {
    asm volatile("st.release.gpu.u32 [%0], %1;" :: "l"(p), "r"(v) : "memory");
}
__device__ __forceinline__ void wait_flag(int q, unsigned target) {
    while (ld_acq(&g_flags[q * 32]) < target) { __nanosleep(16); }
}
__device__ __forceinline__ uint32_t h2u(__half2 h) {
    return *reinterpret_cast<uint32_t*>(&h);
}
__device__ __forceinline__ float sigmoidf_(float x) { return 1.f / (1.f + expf(-x)); }

__device__ __forceinline__ uint2 round4(float4 v) {
    __half2 h0 = __floats2half2_rn(v.x, v.y);
    __half2 h1 = __floats2half2_rn(v.z, v.w);
    return make_uint2(h2u(h0), h2u(h1));
}

// ------------------------- merged prep: X round + W_ih round + bias + flags -
// Grid 2048 CTAs: [0,1024) build Xh from features/embed; [1024,2048) round W_ih.
__global__ void prep_kernel(const float4* __restrict__ features4,
                            const int* __restrict__ captions,
                            const float4* __restrict__ embed4,
                            const float4* __restrict__ Wih4,
                            const float4* __restrict__ b_ih4,
                            const float4* __restrict__ b_hh4)
{
    int cb = blockIdx.x;
    if (cb < 1024) {
        int i = cb * 256 + threadIdx.x;     // over T*B*E/4 = 262,144
        int e4 = i & 127;
        int b  = (i >> 7) & (B_ - 1);
        int t  = i >> 12;
        float4 v;
        if (t == 0) {
            v = features4[b * 128 + e4];
        } else {
            int tok = captions[b * T_ + (t - 1)];
            tok = min(max(tok, 0), V_ - 1);
            v = embed4[(size_t)tok * 128 + e4];
        }
        ((uint2*)g_Xh)[i] = round4(v);
        if (i < G_ / 4) {
            float4 a = b_ih4[i], c = b_hh4[i];
            ((float4*)g_biasg)[i] = make_float4(a.x + c.x, a.y + c.y, a.z + c.z, a.w + c.w);
        }
        if (i < LNCTA * 32) g_flags[i] = 0;
    } else {
        int i = (cb - 1024) * 256 + threadIdx.x;   // over G*E/4 = 262,144
        ((uint2*)g_Wih_h)[i] = round4(Wih4[i]);
    }
}

// ------------------------- Gin GEMM (fp16 1-pass, cp.async pipelined) -------
// Gin[t][n][b] = Xh @ Wih_h^T + bias    (both fp16-rounded)
#define TS 40
#define TILE_B (128 * TS * 2)

__global__ void __launch_bounds__(256, 2)
gin_gemm(const __half* __restrict__ Ah, const __half* __restrict__ Bh,
         const float* __restrict__ bias, float* __restrict__ C)
{
    constexpr int NT = 2;
    constexpr int STAGE = NT * TILE_B;

    extern __shared__ uint8_t dyn[];
    float* bias_s = (float*)(dyn + 2 * STAGE);

    const int tid  = threadIdx.x;
    const int wid  = tid >> 5;
    const int lane = tid & 31;
    const int n0   = blockIdx.x * 128;
    const int m0   = blockIdx.y * 128;

    const int mbase = (wid >> 1) * 32;
    const int nbase = (wid & 1) * 64;

    for (int i = tid; i < 128; i += 256) bias_s[i] = bias[n0 + i];

    const int rowA  = mbase + (lane & 15);
    const int colA8 = (lane >> 4) << 3;
    const int g2    = lane >> 3;
    const int rowB  = nbase + ((g2 & 2) << 2) + (lane & 7);
    const int colB8 = (g2 & 1) << 3;

    const uint32_t sbase = smem_u32(dyn);

    const uint4* gsrc[2] = {
        (const uint4*)(Ah + (size_t)m0 * 512),
        (const uint4*)(Bh + (size_t)n0 * 512) };

    float d[2][8][4];
#pragma unroll
    for (int i = 0; i < 2; i++)
#pragma unroll
        for (int j = 0; j < 8; j++)
#pragma unroll
            for (int q = 0; q < 4; q++) d[i][j][q] = 0.f;

#pragma unroll
    for (int it = 0; it < 4; ++it) {
        int s = tid + it * 256, mat = s >> 9, rem = s & 511, row = rem >> 2, q = rem & 3;
        cpa16(sbase + mat * TILE_B + (row * TS + q * 8) * 2,
              gsrc[mat] + (size_t)row * 64 + q);
    }
    CP_COMMIT();

    for (int kc = 0; kc < 16; ++kc) {
        const int cur = kc & 1;
        if (kc < 15) {
            const uint32_t st = sbase + (cur ^ 1) * STAGE;
#pragma unroll
            for (int it = 0; it < 4; ++it) {
                int s = tid + it * 256, mat = s >> 9, rem = s & 511, row = rem >> 2, q = rem & 3;
                cpa16(st + mat * TILE_B + (row * TS + q * 8) * 2,
                      gsrc[mat] + (size_t)row * 64 + (kc + 1) * 4 + q);
            }
            CP_COMMIT();
            CP_WAIT(1);
        } else {
            CP_WAIT(0);
        }
        __syncthreads();

        const uint32_t aAh = sbase + cur * STAGE;
        const uint32_t aBh = aAh + TILE_B;
#pragma unroll
        for (int ks = 0; ks < 2; ++ks) {
            uint32_t a[2][4], b[8][2];
#pragma unroll
            for (int mb = 0; mb < 2; ++mb)
                ldsm4(a[mb][0], a[mb][1], a[mb][2], a[mb][3],
                      aAh + ((rowA + mb * 16) * TS + ks * 16 + colA8) * 2);
#pragma unroll
            for (int nbp = 0; nbp < 4; ++nbp)
                ldsm4(b[2*nbp][0], b[2*nbp][1], b[2*nbp+1][0], b[2*nbp+1][1],
                      aBh + ((rowB + nbp * 16) * TS + ks * 16 + colB8) * 2);
#pragma unroll
            for (int mb = 0; mb < 2; ++mb)
#pragma unroll
                for (int nb = 0; nb < 8; ++nb)
                    mma_f16(d[mb][nb], a[mb], b[nb]);
        }
        __syncthreads();
    }

    const int gq = lane >> 2, tq = lane & 3;
#pragma unroll
    for (int mb = 0; mb < 2; ++mb) {
#pragma unroll
        for (int half = 0; half < 2; ++half) {
            int m = m0 + mbase + mb * 16 + gq + half * 8;
#pragma unroll
            for (int nb = 0; nb < 8; ++nb) {
                int nl = nbase + nb * 8 + tq * 2;
                int n  = n0 + nl;
                size_t base = (size_t)(m >> 5) * (G_ * B_) + (m & 31);
                C[base + (size_t)n * B_]       = d[mb][nb][half * 2 + 0] + bias_s[nl];
                C[base + (size_t)(n + 1) * B_] = d[mb][nb][half * 2 + 1] + bias_s[nl + 1];
            }
        }
    }
}

// ------------------------- fused persistent LSTM + FC (R14, unchanged) ------
#define LTS 520
#define L_WROW (32 * LTS * 2)               // 33280
#define OFF_WH 0
#define OFF_AH (OFF_WH + L_WROW)
#define OFF_GT (OFF_AH + L_WROW)
#define LSMEM  (OFF_GT + 32 * 33 * 4)       // 70784
// FC layout
#define FTS 520
#define OFF_FB   0
#define FB_BYTES (128 * FTS * 2)            // 133120
#define OFF_FAH  (OFF_FB + FB_BYTES)
#define OFF_FBS  (OFF_FAH + 32 * FTS * 2)   // 166400
#define FSMEM    (OFF_FBS + 512)            // 166912
#define FUSED_SMEM (FSMEM > LSMEM ? FSMEM : LSMEM)

__global__ void __launch_bounds__(256, 1)
fused_lstm_fc(const float* __restrict__ Whh, const float* __restrict__ fcW,
              const float* __restrict__ fc_b, float* __restrict__ out)
{
    extern __shared__ uint8_t dyn[];
    const int tid  = threadIdx.x;
    const int bx   = blockIdx.x;
    const int w    = tid >> 5;
    const int lane = tid & 31;
    const uint32_t sb = smem_u32(dyn);
    const int srcq = tid & 63;

    if (bx < LNCTA) {
        // =================== LSTM role ===================
        float* gates = (float*)(dyn + OFF_GT);
        const uint32_t aWH = sb + OFF_WH;
        const uint32_t aAH = sb + OFF_AH;

        // load W_hh slice fp32 -> fp16 (round) -> smem (one-time)
        {
            const float4* ws = (const float4*)Whh;
#pragma unroll 4
            for (int it = 0; it < 16; ++it) {
                int idx = tid + it * 256;
                int r = idx >> 7, qf = idx & 127;
                int gr = (r >> 3) * 512 + bx * 8 + (r & 7);
                float4 v = ws[(size_t)gr * 128 + qf];
                __half2 h0 = __floats2half2_rn(v.x, v.y);
                __half2 h1 = __floats2half2_rn(v.z, v.w);
                *(uint2*)(dyn + OFF_WH + (r * LTS + qf * 4) * 2)
                    = make_uint2(h2u(h0), h2u(h1));
            }
        }

        const int mt = w & 1;
        const int nt = w >> 1;
        const int rowA  = mt * 16 + (lane & 15);
        const int colA8 = (lane >> 4) << 3;
        const int rowB  = nt * 8 + (lane & 7);
        const int colB8 = (lane >> 3) << 3;
        const int gq = lane >> 2, tq = lane & 3;

        float c_state = 0.f;
        const int jh = bx * 8 + w;
        __syncthreads();

        for (int t = 0; t < 64; ++t) {
            float gpre[4];
#pragma unroll
            for (int g = 0; g < 4; ++g)
                gpre[g] = __ldcg(&g_Gin[(size_t)t * (G_ * B_)
                                        + (size_t)(g * 512 + jh) * B_ + lane]);

            if (t > 0) {
                // ---- dataflow staging: wait on my producer, stage its slice ----
                wait_flag(srcq, (unsigned)t);
                const uint4* hh = (const uint4*)(g_hsb + (size_t)(t - 1) * B_ * H_);
#pragma unroll
                for (int it = 0; it < 8; ++it) {
                    int idx = tid + it * 256;          // = b*64 + srcq
                    int b = idx >> 6;
                    cpa16(aAH + (b * LTS + srcq * 8) * 2, hh + idx);
                }
                CP_COMMIT();
                CP_WAIT(0);
                __syncthreads();

                // ---- gates = h @ W_hi^T : 1 pass x 32 k-steps ----
                float d0[4] = {0, 0, 0, 0};
#pragma unroll
                for (int kb = 0; kb < 16; ++kb) {
                    uint32_t aH0[4], aH1[4], bH[4];
                    ldsm4(aH0[0],aH0[1],aH0[2],aH0[3], aAH + (rowA*LTS + kb*32      + colA8)*2);
                    ldsm4(aH1[0],aH1[1],aH1[2],aH1[3], aAH + (rowA*LTS + kb*32 + 16 + colA8)*2);
                    ldsm4(bH[0],bH[1],bH[2],bH[3],     aWH + (rowB*LTS + kb*32 + colB8)*2);
                    mma_f16(d0, aH0, bH + 0);
                    mma_f16(d0, aH1, bH + 2);
                }
                {
                    int r0 = mt * 16 + gq;
                    int cc = nt * 8 + tq * 2;
                    gates[r0 * 33 + cc]           = d0[0];
                    gates[r0 * 33 + cc + 1]       = d0[1];
                    gates[(r0 + 8) * 33 + cc]     = d0[2];
                    gates[(r0 + 8) * 33 + cc + 1] = d0[3];
                }
            }
            __syncthreads();

            {
                const int b = lane;
                float gv[4];
#pragma unroll
                for (int g = 0; g < 4; ++g) {
                    float s = gpre[g];
                    if (t > 0) s += gates[b * 33 + g * 8 + w];
                    gv[g] = s;
                }
                float i_ = sigmoidf_(gv[0]);
                float f_ = sigmoidf_(gv[1]);
                float gg = tanhf(gv[2]);
                float o_ = sigmoidf_(gv[3]);
                c_state = f_ * c_state + i_ * gg;
                float h = o_ * tanhf(c_state);
                g_hsb[(size_t)t * B_ * H_ + b * 512 + jh] = __float2half(h);
            }

            __syncthreads();
            if (tid == 0) st_rel(&g_flags[bx * 32], (unsigned)(t + 1));
        }
    } else {
        // =================== FC worker role ===================
        const int j = bx - LNCTA;            // 0..78
        const int n0 = j * 128;
        float* bias_s = (float*)(dyn + OFF_FBS);
        const uint32_t aFB = sb + OFF_FB;
        const uint32_t aAH = sb + OFF_FAH;

        // load fc_W tile fp32 -> fp16 -> smem (one-time, hidden behind step 0)
        {
            const float4* fw = (const float4*)fcW;
#pragma unroll 8
            for (int it = 0; it < 64; ++it) {
                int idx = tid + it * 256;
                int r = idx >> 7, qf = idx & 127;
                int n = n0 + r;
                float4 v = (n < V_) ? fw[(size_t)n * 128 + qf]
                                    : make_float4(0.f, 0.f, 0.f, 0.f);
                __half2 h0 = __floats2half2_rn(v.x, v.y);
                __half2 h1 = __floats2half2_rn(v.z, v.w);
                *(uint2*)(dyn + OFF_FB + (r * FTS + qf * 4) * 2)
                    = make_uint2(h2u(h0), h2u(h1));
            }
        }
        for (int i = tid; i < 128; i += 256) {
            int n = n0 + i;
            bias_s[i] = (n < V_) ? fc_b[n] : 0.f;
        }
        __syncthreads();

        const int rowA  = lane & 15;
        const int colA8 = (lane >> 4) << 3;
        const int g2    = lane >> 3;
        const int rowB  = w * 16 + ((g2 & 2) << 2) + (lane & 7);
        const int colB8 = (g2 & 1) << 3;
        const int gq = lane >> 2, tq = lane & 3;

        for (int t = 0; t < 64; ++t) {
            wait_flag(srcq, (unsigned)(t + 1));
            {
                const uint4* hh = (const uint4*)(g_hsb + (size_t)t * B_ * H_);
#pragma unroll
                for (int it = 0; it < 8; ++it) {
                    int idx = tid + it * 256;
                    int b = idx >> 6;
                    cpa16(aAH + (b * FTS + srcq * 8) * 2, hh + idx);
                }
                CP_COMMIT();
                CP_WAIT(0);
                __syncthreads();
            }

            float d[2][2][4];
#pragma unroll
            for (int i = 0; i < 2; i++)
#pragma unroll
                for (int jn = 0; jn < 2; jn++)
#pragma unroll
                    for (int q = 0; q < 4; q++) d[i][jn][q] = 0.f;
#pragma unroll
            for (int kb = 0; kb < 32; ++kb) {
                uint32_t aH[2][4], b[2][2];
                ldsm4(aH[0][0],aH[0][1],aH[0][2],aH[0][3], aAH + ((rowA     )*FTS + kb*16 + colA8)*2);
                ldsm4(aH[1][0],aH[1][1],aH[1][2],aH[1][3], aAH + ((rowA + 16)*FTS + kb*16 + colA8)*2);
                ldsm4(b[0][0], b[0][1], b[1][0], b[1][1],  aFB + (rowB*FTS + kb*16 + colB8)*2);
#pragma unroll
                for (int mb = 0; mb < 2; ++mb)
#pragma unroll
                    for (int nb = 0; nb < 2; ++nb)
                        mma_f16(d[mb][nb], aH[mb], b[nb]);
            }

#pragma unroll
            for (int mb = 0; mb < 2; ++mb) {
#pragma unroll
                for (int half = 0; half < 2; ++half) {
                    int b = mb * 16 + gq + half * 8;
                    float* crow = out + (size_t)b * (T_ * V_) + (size_t)t * V_;
#pragma unroll
                    for (int nb = 0; nb < 2; ++nb) {
                        int nl = w * 16 + nb * 8 + tq * 2;
                        int n  = n0 + nl;
                        if (n < V_) {
                            float2 o;
                            o.x = d[mb][nb][half * 2 + 0] + bias_s[nl];
                            o.y = d[mb][nb][half * 2 + 1] + bias_s[nl + 1];
                            *(float2*)&crow[n] = o;
                        }
                    }
                }
            }
            __syncthreads();
        }
    }
}

// ------------------------- launch ------------------------------------------
extern "C" void kernel_launch(void* const* d_in, const int* in_sizes, int n_in,
                              void* d_out, int out_size)
{
    const float* features = (const float*)d_in[0];
    const int*   captions = (const int*)d_in[1];
    // d_in[2] = forward_approach (unused)
    const float* embed = (const float*)d_in[3];
    const float* W_ih  = (const float*)d_in[4];
    const float* W_hh  = (const float*)d_in[5];
    const float* b_ih  = (const float*)d_in[6];
    const float* b_hh  = (const float*)d_in[7];
    const float* fc_W  = (const float*)d_in[8];
    const float* fc_b  = (const float*)d_in[9];
    float* out = (float*)d_out;

    float *pGin, *pbias;
    __half *pXh, *pWih_h;
    cudaGetSymbolAddress((void**)&pGin,   g_Gin);
    cudaGetSymbolAddress((void**)&pbias,  g_biasg);
    cudaGetSymbolAddress((void**)&pXh,    g_Xh);
    cudaGetSymbolAddress((void**)&pWih_h, g_Wih_h);

    const int SMEM_G1 = 2 * 2 * TILE_B + 512;    // 41472
    cudaFuncSetAttribute(gin_gemm, cudaFuncAttributeMaxDynamicSharedMemorySize, SMEM_G1);
    cudaFuncSetAttribute(fused_lstm_fc, cudaFuncAttributeMaxDynamicSharedMemorySize, FUSED_SMEM);

    // 1) merged prep: X fp16 + W_ih fp16 + fused bias + flag reset (one launch)
    prep_kernel<<<2048, 256>>>(
        (const float4*)features, captions, (const float4*)embed,
        (const float4*)W_ih, (const float4*)b_ih, (const float4*)b_hh);

    // 2) Gin[t][n][b] = Xh @ Wih_h^T + (b_ih + b_hh)   (fp16 1-pass)
    gin_gemm<<<dim3(G_ / 128, (T_ * B_) / 128), 256, SMEM_G1>>>(
        pXh, pWih_h, pbias, pGin);

    // 3) fused persistent LSTM + FC (unchanged from R14)
    fused_lstm_fc<<<LNCTA + FNCTA, 256, FUSED_SMEM>>>(W_hh, fc_W, fc_b, out);
}

// round 16
// speedup vs baseline: 1.2381x; 1.0687x over previous
#include <cuda_runtime.h>
#include <cuda_fp16.h>
#include <math.h>
#include <stdint.h>

#define B_  32
#define T_  64
#define E_  512
#define H_  512
#define V_  10000
#define G_  2048          // 4*H
#define LNCTA 64          // LSTM CTAs
#define FNCTA 79          // FC worker CTAs

// ------------------------- device scratch (no allocs allowed) ---------------
__device__ __half g_Xh  [T_ * B_ * E_];
__device__ __half g_Wih_h[G_ * E_];
__device__ __half g_hsb [T_ * B_ * H_];   // h history, fp16, b-major per t
__device__ float g_Gin [T_ * G_ * B_];    // [t][n][b]
__device__ float g_biasg[G_];
__device__ unsigned g_flags[LNCTA * 32];  // 128B-strided per-CTA step flags

// ------------------------- helpers (baseline PTX, sm_80+) -------------------
__device__ __forceinline__ uint32_t smem_u32(const void* p) {
    uint32_t a;
    asm("{ .reg .u64 t; cvta.to.shared.u64 t, %1; cvt.u32.u64 %0, t; }"
        : "=r"(a) : "l"(p));
    return a;
}
__device__ __forceinline__ void ldsm4(uint32_t& r0, uint32_t& r1,
                                      uint32_t& r2, uint32_t& r3, uint32_t addr) {
    asm volatile("ldmatrix.sync.aligned.m8n8.x4.shared.b16 {%0,%1,%2,%3}, [%4];"
                 : "=r"(r0), "=r"(r1), "=r"(r2), "=r"(r3) : "r"(addr));
}
__device__ __forceinline__ void mma_f16(float* d, const uint32_t* a, const uint32_t* b) {
    asm volatile(
        "mma.sync.aligned.m16n8k16.row.col.f32.f16.f16.f32 "
        "{%0,%1,%2,%3}, {%4,%5,%6,%7}, {%8,%9}, {%0,%1,%2,%3};"
        : "+f"(d[0]), "+f"(d[1]), "+f"(d[2]), "+f"(d[3])
        : "r"(a[0]), "r"(a[1]), "r"(a[2]), "r"(a[3]), "r"(b[0]), "r"(b[1]));
}
__device__ __forceinline__ void cpa16(uint32_t saddr, const void* g) {
    asm volatile("cp.async.cg.shared.global [%0], [%1], 16;" :: "r"(saddr), "l"(g));
}
#define CP_COMMIT() asm volatile("cp.async.commit_group;" ::: "memory")
#define CP_WAIT(n)  asm volatile("cp.async.wait_group %0;" :: "n"(n) : "memory")

__device__ __forceinline__ unsigned ld_acq(const unsigned* p) {
    unsigned v;
    asm volatile("ld.acquire.gpu.u32 %0, [%1];" : "=r"(v) : "l"(p) : "memory");
    return v;
}
__device__ __forceinline__ void st_rel(unsigned* p, unsigned v) {
    asm volatile("st.release.gpu.u32 [%0], %1;" :: "l"(p), "r"(v) : "memory");
}
__device__ __forceinline__ void wait_flag(int q, unsigned target) {
    while (ld_acq(&g_flags[q * 32]) < target) { __nanosleep(16); }
}
__device__ __forceinline__ uint32_t h2u(__half2 h) {
    return *reinterpret_cast<uint32_t*>(&h);
}
__device__ __forceinline__ float sigmoidf_(float x) { return 1.f / (1.f + expf(-x)); }

__device__ __forceinline__ uint2 round4(float4 v) {
    __half2 h0 = __floats2half2_rn(v.x, v.y);
    __half2 h1 = __floats2half2_rn(v.z, v.w);
    return make_uint2(h2u(h0), h2u(h1));
}

// ------------------------- merged prep: X round + W_ih round + bias + flags -
__global__ void prep_kernel(const float4* __restrict__ features4,
                            const int* __restrict__ captions,
                            const float4* __restrict__ embed4,
                            const float4* __restrict__ Wih4,
                            const float4* __restrict__ b_ih4,
                            const float4* __restrict__ b_hh4)
{
    int cb = blockIdx.x;
    if (cb < 1024) {
        int i = cb * 256 + threadIdx.x;     // over T*B*E/4 = 262,144
        int e4 = i & 127;
        int b  = (i >> 7) & (B_ - 1);
        int t  = i >> 12;
        float4 v;
        if (t == 0) {
            v = features4[b * 128 + e4];
        } else {
            int tok = captions[b * T_ + (t - 1)];
            tok = min(max(tok, 0), V_ - 1);
            v = embed4[(size_t)tok * 128 + e4];
        }
        ((uint2*)g_Xh)[i] = round4(v);
        if (i < G_ / 4) {
            float4 a = b_ih4[i], c = b_hh4[i];
            ((float4*)g_biasg)[i] = make_float4(a.x + c.x, a.y + c.y, a.z + c.z, a.w + c.w);
        }
        if (i < LNCTA * 32) g_flags[i] = 0;
    } else {
        int i = (cb - 1024) * 256 + threadIdx.x;   // over G*E/4 = 262,144
        ((uint2*)g_Wih_h)[i] = round4(Wih4[i]);
    }
}

// ------------------------- Gin GEMM (fp16 1-pass, cp.async pipelined) -------
#define TS 40
#define TILE_B (128 * TS * 2)

__global__ void __launch_bounds__(256, 2)
gin_gemm(const __half* __restrict__ Ah, const __half* __restrict__ Bh,
         const float* __restrict__ bias, float* __restrict__ C)
{
    constexpr int NT = 2;
    constexpr int STAGE = NT * TILE_B;

    extern __shared__ uint8_t dyn[];
    float* bias_s = (float*)(dyn + 2 * STAGE);

    const int tid  = threadIdx.x;
    const int wid  = tid >> 5;
    const int lane = tid & 31;
    const int n0   = blockIdx.x * 128;
    const int m0   = blockIdx.y * 128;

    const int mbase = (wid >> 1) * 32;
    const int nbase = (wid & 1) * 64;

    for (int i = tid; i < 128; i += 256) bias_s[i] = bias[n0 + i];

    const int rowA  = mbase + (lane & 15);
    const int colA8 = (lane >> 4) << 3;
    const int g2    = lane >> 3;
    const int rowB  = nbase + ((g2 & 2) << 2) + (lane & 7);
    const int colB8 = (g2 & 1) << 3;

    const uint32_t sbase = smem_u32(dyn);

    const uint4* gsrc[2] = {
        (const uint4*)(Ah + (size_t)m0 * 512),
        (const uint4*)(Bh + (size_t)n0 * 512) };

    float d[2][8][4];
#pragma unroll
    for (int i = 0; i < 2; i++)
#pragma unroll
        for (int j = 0; j < 8; j++)
#pragma unroll
            for (int q = 0; q < 4; q++) d[i][j][q] = 0.f;

#pragma unroll
    for (int it = 0; it < 4; ++it) {
        int s = tid + it * 256, mat = s >> 9, rem = s & 511, row = rem >> 2, q = rem & 3;
        cpa16(sbase + mat * TILE_B + (row * TS + q * 8) * 2,
              gsrc[mat] + (size_t)row * 64 + q);
    }
    CP_COMMIT();

    for (int kc = 0; kc < 16; ++kc) {
        const int cur = kc & 1;
        if (kc < 15) {
            const uint32_t st = sbase + (cur ^ 1) * STAGE;
#pragma unroll
            for (int it = 0; it < 4; ++it) {
                int s = tid + it * 256, mat = s >> 9, rem = s & 511, row = rem >> 2, q = rem & 3;
                cpa16(st + mat * TILE_B + (row * TS + q * 8) * 2,
                      gsrc[mat] + (size_t)row * 64 + (kc + 1) * 4 + q);
            }
            CP_COMMIT();
            CP_WAIT(1);
        } else {
            CP_WAIT(0);
        }
        __syncthreads();

        const uint32_t aAh = sbase + cur * STAGE;
        const uint32_t aBh = aAh + TILE_B;
#pragma unroll
        for (int ks = 0; ks < 2; ++ks) {
            uint32_t a[2][4], b[8][2];
#pragma unroll
            for (int mb = 0; mb < 2; ++mb)
                ldsm4(a[mb][0], a[mb][1], a[mb][2], a[mb][3],
                      aAh + ((rowA + mb * 16) * TS + ks * 16 + colA8) * 2);
#pragma unroll
            for (int nbp = 0; nbp < 4; ++nbp)
                ldsm4(b[2*nbp][0], b[2*nbp][1], b[2*nbp+1][0], b[2*nbp+1][1],
                      aBh + ((rowB + nbp * 16) * TS + ks * 16 + colB8) * 2);
#pragma unroll
            for (int mb = 0; mb < 2; ++mb)
#pragma unroll
                for (int nb = 0; nb < 8; ++nb)
                    mma_f16(d[mb][nb], a[mb], b[nb]);
        }
        __syncthreads();
    }

    const int gq = lane >> 2, tq = lane & 3;
#pragma unroll
    for (int mb = 0; mb < 2; ++mb) {
#pragma unroll
        for (int half = 0; half < 2; ++half) {
            int m = m0 + mbase + mb * 16 + gq + half * 8;
#pragma unroll
            for (int nb = 0; nb < 8; ++nb) {
                int nl = nbase + nb * 8 + tq * 2;
                int n  = n0 + nl;
                size_t base = (size_t)(m >> 5) * (G_ * B_) + (m & 31);
                C[base + (size_t)n * B_]       = d[mb][nb][half * 2 + 0] + bias_s[nl];
                C[base + (size_t)(n + 1) * B_] = d[mb][nb][half * 2 + 1] + bias_s[nl + 1];
            }
        }
    }
}

// ------------------------- fused persistent LSTM + FC -----------------------
// R15 structure; ONE change: h published via smem bounce + 32 coalesced
// STG.128 by warp 0 (was 256 scattered 2B stores ahead of the release).
#define LTS 520
#define L_WROW (32 * LTS * 2)               // 33280
#define OFF_WH 0
#define OFF_AH (OFF_WH + L_WROW)
#define OFF_GT (OFF_AH + L_WROW)
#define OFF_HB (OFF_GT + 32 * 33 * 4)       // h bounce: 32 b x 8 jh halves
#define LSMEM  (OFF_HB + 512)               // 71296
// FC layout
#define FTS 520
#define OFF_FB   0
#define FB_BYTES (128 * FTS * 2)            // 133120
#define OFF_FAH  (OFF_FB + FB_BYTES)
#define OFF_FBS  (OFF_FAH + 32 * FTS * 2)   // 166400
#define FSMEM    (OFF_FBS + 512)            // 166912
#define FUSED_SMEM (FSMEM > LSMEM ? FSMEM : LSMEM)

__global__ void __launch_bounds__(256, 1)
fused_lstm_fc(const float* __restrict__ Whh, const float* __restrict__ fcW,
              const float* __restrict__ fc_b, float* __restrict__ out)
{
    extern __shared__ uint8_t dyn[];
    const int tid  = threadIdx.x;
    const int bx   = blockIdx.x;
    const int w    = tid >> 5;
    const int lane = tid & 31;
    const uint32_t sb = smem_u32(dyn);
    const int srcq = tid & 63;

    if (bx < LNCTA) {
        // =================== LSTM role ===================
        float* gates = (float*)(dyn + OFF_GT);
        __half* hbuf = (__half*)(dyn + OFF_HB);
        const uint32_t aWH = sb + OFF_WH;
        const uint32_t aAH = sb + OFF_AH;

        // load W_hh slice fp32 -> fp16 (round) -> smem (one-time)
        {
            const float4* ws = (const float4*)Whh;
#pragma unroll 4
            for (int it = 0; it < 16; ++it) {
                int idx = tid + it * 256;
                int r = idx >> 7, qf = idx & 127;
                int gr = (r >> 3) * 512 + bx * 8 + (r & 7);
                float4 v = ws[(size_t)gr * 128 + qf];
                __half2 h0 = __floats2half2_rn(v.x, v.y);
                __half2 h1 = __floats2half2_rn(v.z, v.w);
                *(uint2*)(dyn + OFF_WH + (r * LTS + qf * 4) * 2)
                    = make_uint2(h2u(h0), h2u(h1));
            }
        }

        const int mt = w & 1;
        const int nt = w >> 1;
        const int rowA  = mt * 16 + (lane & 15);
        const int colA8 = (lane >> 4) << 3;
        const int rowB  = nt * 8 + (lane & 7);
        const int colB8 = (lane >> 3) << 3;
        const int gq = lane >> 2, tq = lane & 3;

        float c_state = 0.f;
        const int jh = bx * 8 + w;
        __syncthreads();

        for (int t = 0; t < 64; ++t) {
            float gpre[4];
#pragma unroll
            for (int g = 0; g < 4; ++g)
                gpre[g] = __ldcg(&g_Gin[(size_t)t * (G_ * B_)
                                        + (size_t)(g * 512 + jh) * B_ + lane]);

            if (t > 0) {
                // ---- dataflow staging: wait on my producer, stage its slice ----
                wait_flag(srcq, (unsigned)t);
                const uint4* hh = (const uint4*)(g_hsb + (size_t)(t - 1) * B_ * H_);
#pragma unroll
                for (int it = 0; it < 8; ++it) {
                    int idx = tid + it * 256;          // = b*64 + srcq
                    int b = idx >> 6;
                    cpa16(aAH + (b * LTS + srcq * 8) * 2, hh + idx);
                }
                CP_COMMIT();
                CP_WAIT(0);
                __syncthreads();

                // ---- gates = h @ W_hi^T : 1 pass x 32 k-steps ----
                float d0[4] = {0, 0, 0, 0};
#pragma unroll
                for (int kb = 0; kb < 16; ++kb) {
                    uint32_t aH0[4], aH1[4], bH[4];
                    ldsm4(aH0[0],aH0[1],aH0[2],aH0[3], aAH + (rowA*LTS + kb*32      + colA8)*2);
                    ldsm4(aH1[0],aH1[1],aH1[2],aH1[3], aAH + (rowA*LTS + kb*32 + 16 + colA8)*2);
                    ldsm4(bH[0],bH[1],bH[2],bH[3],     aWH + (rowB*LTS + kb*32 + colB8)*2);
                    mma_f16(d0, aH0, bH + 0);
                    mma_f16(d0, aH1, bH + 2);
                }
                {
                    int r0 = mt * 16 + gq;
                    int cc = nt * 8 + tq * 2;
                    gates[r0 * 33 + cc]           = d0[0];
                    gates[r0 * 33 + cc + 1]       = d0[1];
                    gates[(r0 + 8) * 33 + cc]     = d0[2];
                    gates[(r0 + 8) * 33 + cc + 1] = d0[3];
                }
            }
            __syncthreads();

            {
                const int b = lane;
                float gv[4];
#pragma unroll
                for (int g = 0; g < 4; ++g) {
                    float s = gpre[g];
                    if (t > 0) s += gates[b * 33 + g * 8 + w];
                    gv[g] = s;
                }
                float i_ = sigmoidf_(gv[0]);
                float f_ = sigmoidf_(gv[1]);
                float gg = tanhf(gv[2]);
                float o_ = sigmoidf_(gv[3]);
                c_state = f_ * c_state + i_ * gg;
                float h = o_ * tanhf(c_state);
                hbuf[b * 8 + w] = __float2half(h);     // smem bounce
            }
            __syncthreads();

            // ---- coalesced publish: warp 0 stores 32 x 16B rows ----
            if (tid < 32)
                *(uint4*)(g_hsb + (size_t)t * B_ * H_ + tid * 512 + bx * 8)
                    = *(const uint4*)(hbuf + tid * 8);
            __syncthreads();
            if (tid == 0) st_rel(&g_flags[bx * 32], (unsigned)(t + 1));
        }
    } else {
        // =================== FC worker role ===================
        const int j = bx - LNCTA;            // 0..78
        const int n0 = j * 128;
        float* bias_s = (float*)(dyn + OFF_FBS);
        const uint32_t aFB = sb + OFF_FB;
        const uint32_t aAH = sb + OFF_FAH;

        // load fc_W tile fp32 -> fp16 -> smem (one-time, hidden behind step 0)
        {
            const float4* fw = (const float4*)fcW;
#pragma unroll 8
            for (int it = 0; it < 64; ++it) {
                int idx = tid + it * 256;
                int r = idx >> 7, qf = idx & 127;
                int n = n0 + r;
                float4 v = (n < V_) ? fw[(size_t)n * 128 + qf]
                                    : make_float4(0.f, 0.f, 0.f, 0.f);
                __half2 h0 = __floats2half2_rn(v.x, v.y);
                __half2 h1 = __floats2half2_rn(v.z, v.w);
                *(uint2*)(dyn + OFF_FB + (r * FTS + qf * 4) * 2)
                    = make_uint2(h2u(h0), h2u(h1));
            }
        }
        for (int i = tid; i < 128; i += 256) {
            int n = n0 + i;
            bias_s[i] = (n < V_) ? fc_b[n] : 0.f;
        }
        __syncthreads();

        const int rowA  = lane & 15;
        const int colA8 = (lane >> 4) << 3;
        const int g2    = lane >> 3;
        const int rowB  = w * 16 + ((g2 & 2) << 2) + (lane & 7);
        const int colB8 = (g2 & 1) << 3;
        const int gq = lane >> 2, tq = lane & 3;

        for (int t = 0; t < 64; ++t) {
            wait_flag(srcq, (unsigned)(t + 1));
            {
                const uint4* hh = (const uint4*)(g_hsb + (size_t)t * B_ * H_);
#pragma unroll
                for (int it = 0; it < 8; ++it) {
                    int idx = tid + it * 256;
                    int b = idx >> 6;
                    cpa16(aAH + (b * FTS + srcq * 8) * 2, hh + idx);
                }
                CP_COMMIT();
                CP_WAIT(0);
                __syncthreads();
            }

            float d[2][2][4];
#pragma unroll
            for (int i = 0; i < 2; i++)
#pragma unroll
                for (int jn = 0; jn < 2; jn++)
#pragma unroll
                    for (int q = 0; q < 4; q++) d[i][jn][q] = 0.f;
#pragma unroll
            for (int kb = 0; kb < 32; ++kb) {
                uint32_t aH[2][4], b[2][2];
                ldsm4(aH[0][0],aH[0][1],aH[0][2],aH[0][3], aAH + ((rowA     )*FTS + kb*16 + colA8)*2);
                ldsm4(aH[1][0],aH[1][1],aH[1][2],aH[1][3], aAH + ((rowA + 16)*FTS + kb*16 + colA8)*2);
                ldsm4(b[0][0], b[0][1], b[1][0], b[1][1],  aFB + (rowB*FTS + kb*16 + colB8)*2);
#pragma unroll
                for (int mb = 0; mb < 2; ++mb)
#pragma unroll
                    for (int nb = 0; nb < 2; ++nb)
                        mma_f16(d[mb][nb], aH[mb], b[nb]);
            }

#pragma unroll
            for (int mb = 0; mb < 2; ++mb) {
#pragma unroll
                for (int half = 0; half < 2; ++half) {
                    int b = mb * 16 + gq + half * 8;
                    float* crow = out + (size_t)b * (T_ * V_) + (size_t)t * V_;
#pragma unroll
                    for (int nb = 0; nb < 2; ++nb) {
                        int nl = w * 16 + nb * 8 + tq * 2;
                        int n  = n0 + nl;
                        if (n < V_) {
                            float2 o;
                            o.x = d[mb][nb][half * 2 + 0] + bias_s[nl];
                            o.y = d[mb][nb][half * 2 + 1] + bias_s[nl + 1];
                            *(float2*)&crow[n] = o;
                        }
                    }
                }
            }
            __syncthreads();
        }
    }
}

// ------------------------- launch ------------------------------------------
extern "C" void kernel_launch(void* const* d_in, const int* in_sizes, int n_in,
                              void* d_out, int out_size)
{
    const float* features = (const float*)d_in[0];
    const int*   captions = (const int*)d_in[1];
    // d_in[2] = forward_approach (unused)
    const float* embed = (const float*)d_in[3];
    const float* W_ih  = (const float*)d_in[4];
    const float* W_hh  = (const float*)d_in[5];
    const float* b_ih  = (const float*)d_in[6];
    const float* b_hh  = (const float*)d_in[7];
    const float* fc_W  = (const float*)d_in[8];
    const float* fc_b  = (const float*)d_in[9];
    float* out = (float*)d_out;

    float *pGin, *pbias;
    __half *pXh, *pWih_h;
    cudaGetSymbolAddress((void**)&pGin,   g_Gin);
    cudaGetSymbolAddress((void**)&pbias,  g_biasg);
    cudaGetSymbolAddress((void**)&pXh,    g_Xh);
    cudaGetSymbolAddress((void**)&pWih_h, g_Wih_h);

    const int SMEM_G1 = 2 * 2 * TILE_B + 512;    // 41472
    cudaFuncSetAttribute(gin_gemm, cudaFuncAttributeMaxDynamicSharedMemorySize, SMEM_G1);
    cudaFuncSetAttribute(fused_lstm_fc, cudaFuncAttributeMaxDynamicSharedMemorySize, FUSED_SMEM);

    // 1) merged prep: X fp16 + W_ih fp16 + fused bias + flag reset (one launch)
    prep_kernel<<<2048, 256>>>(
        (const float4*)features, captions, (const float4*)embed,
        (const float4*)W_ih, (const float4*)b_ih, (const float4*)b_hh);

    // 2) Gin[t][n][b] = Xh @ Wih_h^T + (b_ih + b_hh)   (fp16 1-pass)
    gin_gemm<<<dim3(G_ / 128, (T_ * B_) / 128), 256, SMEM_G1>>>(
        pXh, pWih_h, pbias, pGin);

    // 3) fused persistent LSTM + FC (coalesced h publish)
    fused_lstm_fc<<<LNCTA + FNCTA, 256, FUSED_SMEM>>>(W_hh, fc_W, fc_b, out);
}

// round 17
// speedup vs baseline: 1.3807x; 1.1152x over previous
#include <cuda_runtime.h>
#include <cuda_fp16.h>
#include <math.h>
#include <stdint.h>

#define B_  32
#define T_  64
#define E_  512
#define H_  512
#define V_  10000
#define G_  2048          // 4*H
#define LNCTA 64          // LSTM CTAs
#define FNCTA 79          // FC worker CTAs

// ------------------------- device scratch (no allocs allowed) ---------------
__device__ __half g_Xh  [T_ * B_ * E_];
__device__ __half g_Wih_h[G_ * E_];
__device__ __half g_hsb [T_ * B_ * H_];   // h history, fp16, b-major per t
__device__ float g_Gin [T_ * G_ * B_];    // [t][n][b]
__device__ float g_biasg[G_];
__device__ unsigned g_flags[LNCTA * 32];  // 128B-strided per-CTA step flags

// ------------------------- helpers (baseline PTX, sm_80+) -------------------
__device__ __forceinline__ uint32_t smem_u32(const void* p) {
    uint32_t a;
    asm("{ .reg .u64 t; cvta.to.shared.u64 t, %1; cvt.u32.u64 %0, t; }"
        : "=r"(a) : "l"(p));
    return a;
}
__device__ __forceinline__ void ldsm4(uint32_t& r0, uint32_t& r1,
                                      uint32_t& r2, uint32_t& r3, uint32_t addr) {
    asm volatile("ldmatrix.sync.aligned.m8n8.x4.shared.b16 {%0,%1,%2,%3}, [%4];"
                 : "=r"(r0), "=r"(r1), "=r"(r2), "=r"(r3) : "r"(addr));
}
__device__ __forceinline__ void mma_f16(float* d, const uint32_t* a, const uint32_t* b) {
    asm volatile(
        "mma.sync.aligned.m16n8k16.row.col.f32.f16.f16.f32 "
        "{%0,%1,%2,%3}, {%4,%5,%6,%7}, {%8,%9}, {%0,%1,%2,%3};"
        : "+f"(d[0]), "+f"(d[1]), "+f"(d[2]), "+f"(d[3])
        : "r"(a[0]), "r"(a[1]), "r"(a[2]), "r"(a[3]), "r"(b[0]), "r"(b[1]));
}
__device__ __forceinline__ void cpa16(uint32_t saddr, const void* g) {
    asm volatile("cp.async.cg.shared.global [%0], [%1], 16;" :: "r"(saddr), "l"(g));
}
#define CP_COMMIT() asm volatile("cp.async.commit_group;" ::: "memory")
#define CP_WAIT(n)  asm volatile("cp.async.wait_group %0;" :: "n"(n) : "memory")

__device__ __forceinline__ unsigned ld_acq(const unsigned* p) {
    unsigned v;
    asm volatile("ld.acquire.gpu.u32 %0, [%1];" : "=r"(v) : "l"(p) : "memory");
    return v;
}
__device__ __forceinline__ void st_rel(unsigned* p, unsigned v) {
    asm volatile("st.release.gpu.u32 [%0], %1;" :: "l"(p), "r"(v) : "memory");
}
__device__ __forceinline__ void wait_flag(int q, unsigned target) {
    while (ld_acq(&g_flags[q * 32]) < target) { __nanosleep(16); }
}
__device__ __forceinline__ uint32_t h2u(__half2 h) {
    return *reinterpret_cast<uint32_t*>(&h);
}
__device__ __forceinline__ float sigmoidf_(float x) { return 1.f / (1.f + expf(-x)); }

__device__ __forceinline__ uint2 round4(float4 v) {
    __half2 h0 = __floats2half2_rn(v.x, v.y);
    __half2 h1 = __floats2half2_rn(v.z, v.w);
    return make_uint2(h2u(h0), h2u(h1));
}

// ------------------------- merged prep: X round + W_ih round + bias + flags -
__global__ void prep_kernel(const float4* __restrict__ features4,
                            const int* __restrict__ captions,
                            const float4* __restrict__ embed4,
                            const float4* __restrict__ Wih4,
                            const float4* __restrict__ b_ih4,
                            const float4* __restrict__ b_hh4)
{
    int cb = blockIdx.x;
    if (cb < 1024) {
        int i = cb * 256 + threadIdx.x;     // over T*B*E/4 = 262,144
        int e4 = i & 127;
        int b  = (i >> 7) & (B_ - 1);
        int t  = i >> 12;
        float4 v;
        if (t == 0) {
            v = features4[b * 128 + e4];
        } else {
            int tok = captions[b * T_ + (t - 1)];
            tok = min(max(tok, 0), V_ - 1);
            v = embed4[(size_t)tok * 128 + e4];
        }
        ((uint2*)g_Xh)[i] = round4(v);
        if (i < G_ / 4) {
            float4 a = b_ih4[i], c = b_hh4[i];
            ((float4*)g_biasg)[i] = make_float4(a.x + c.x, a.y + c.y, a.z + c.z, a.w + c.w);
        }
        if (i < LNCTA * 32) g_flags[i] = 0;
    } else {
        int i = (cb - 1024) * 256 + threadIdx.x;   // over G*E/4 = 262,144
        ((uint2*)g_Wih_h)[i] = round4(Wih4[i]);
    }
}

// ------------------------- Gin GEMM (fp16 1-pass, cp.async pipelined) -------
#define TS 40
#define TILE_B (128 * TS * 2)

__global__ void __launch_bounds__(256, 2)
gin_gemm(const __half* __restrict__ Ah, const __half* __restrict__ Bh,
         const float* __restrict__ bias, float* __restrict__ C)
{
    constexpr int NT = 2;
    constexpr int STAGE = NT * TILE_B;

    extern __shared__ uint8_t dyn[];
    float* bias_s = (float*)(dyn + 2 * STAGE);

    const int tid  = threadIdx.x;
    const int wid  = tid >> 5;
    const int lane = tid & 31;
    const int n0   = blockIdx.x * 128;
    const int m0   = blockIdx.y * 128;

    const int mbase = (wid >> 1) * 32;
    const int nbase = (wid & 1) * 64;

    for (int i = tid; i < 128; i += 256) bias_s[i] = bias[n0 + i];

    const int rowA  = mbase + (lane & 15);
    const int colA8 = (lane >> 4) << 3;
    const int g2    = lane >> 3;
    const int rowB  = nbase + ((g2 & 2) << 2) + (lane & 7);
    const int colB8 = (g2 & 1) << 3;

    const uint32_t sbase = smem_u32(dyn);

    const uint4* gsrc[2] = {
        (const uint4*)(Ah + (size_t)m0 * 512),
        (const uint4*)(Bh + (size_t)n0 * 512) };

    float d[2][8][4];
#pragma unroll
    for (int i = 0; i < 2; i++)
#pragma unroll
        for (int j = 0; j < 8; j++)
#pragma unroll
            for (int q = 0; q < 4; q++) d[i][j][q] = 0.f;

#pragma unroll
    for (int it = 0; it < 4; ++it) {
        int s = tid + it * 256, mat = s >> 9, rem = s & 511, row = rem >> 2, q = rem & 3;
        cpa16(sbase + mat * TILE_B + (row * TS + q * 8) * 2,
              gsrc[mat] + (size_t)row * 64 + q);
    }
    CP_COMMIT();

    for (int kc = 0; kc < 16; ++kc) {
        const int cur = kc & 1;
        if (kc < 15) {
            const uint32_t st = sbase + (cur ^ 1) * STAGE;
#pragma unroll
            for (int it = 0; it < 4; ++it) {
                int s = tid + it * 256, mat = s >> 9, rem = s & 511, row = rem >> 2, q = rem & 3;
                cpa16(st + mat * TILE_B + (row * TS + q * 8) * 2,
                      gsrc[mat] + (size_t)row * 64 + (kc + 1) * 4 + q);
            }
            CP_COMMIT();
            CP_WAIT(1);
        } else {
            CP_WAIT(0);
        }
        __syncthreads();

        const uint32_t aAh = sbase + cur * STAGE;
        const uint32_t aBh = aAh + TILE_B;
#pragma unroll
        for (int ks = 0; ks < 2; ++ks) {
            uint32_t a[2][4], b[8][2];
#pragma unroll
            for (int mb = 0; mb < 2; ++mb)
                ldsm4(a[mb][0], a[mb][1], a[mb][2], a[mb][3],
                      aAh + ((rowA + mb * 16) * TS + ks * 16 + colA8) * 2);
#pragma unroll
            for (int nbp = 0; nbp < 4; ++nbp)
                ldsm4(b[2*nbp][0], b[2*nbp][1], b[2*nbp+1][0], b[2*nbp+1][1],
                      aBh + ((rowB + nbp * 16) * TS + ks * 16 + colB8) * 2);
#pragma unroll
            for (int mb = 0; mb < 2; ++mb)
#pragma unroll
                for (int nb = 0; nb < 8; ++nb)
                    mma_f16(d[mb][nb], a[mb], b[nb]);
        }
        __syncthreads();
    }

    const int gq = lane >> 2, tq = lane & 3;
#pragma unroll
    for (int mb = 0; mb < 2; ++mb) {
#pragma unroll
        for (int half = 0; half < 2; ++half) {
            int m = m0 + mbase + mb * 16 + gq + half * 8;
#pragma unroll
            for (int nb = 0; nb < 8; ++nb) {
                int nl = nbase + nb * 8 + tq * 2;
                int n  = n0 + nl;
                size_t base = (size_t)(m >> 5) * (G_ * B_) + (m & 31);
                C[base + (size_t)n * B_]       = d[mb][nb][half * 2 + 0] + bias_s[nl];
                C[base + (size_t)(n + 1) * B_] = d[mb][nb][half * 2 + 1] + bias_s[nl + 1];
            }
        }
    }
}

// ------------------------- fused persistent LSTM + FC -----------------------
// R16 structure; TWO changes:
//  (1) W_hh fragments hoisted into registers before the t-loop (no per-step
//      B ldsm in the gate mma).
//  (2) publish tail uses __syncwarp (STG + release both in warp 0).
#define LTS 520
#define L_WROW (32 * LTS * 2)               // 33280
#define OFF_WH 0
#define OFF_AH (OFF_WH + L_WROW)
#define OFF_GT (OFF_AH + L_WROW)
#define OFF_HB (OFF_GT + 32 * 33 * 4)       // h bounce: 32 b x 8 jh halves
#define LSMEM  (OFF_HB + 512)               // 71296
// FC layout
#define FTS 520
#define OFF_FB   0
#define FB_BYTES (128 * FTS * 2)            // 133120
#define OFF_FAH  (OFF_FB + FB_BYTES)
#define OFF_FBS  (OFF_FAH + 32 * FTS * 2)   // 166400
#define FSMEM    (OFF_FBS + 512)            // 166912
#define FUSED_SMEM (FSMEM > LSMEM ? FSMEM : LSMEM)

__global__ void __launch_bounds__(256, 1)
fused_lstm_fc(const float* __restrict__ Whh, const float* __restrict__ fcW,
              const float* __restrict__ fc_b, float* __restrict__ out)
{
    extern __shared__ uint8_t dyn[];
    const int tid  = threadIdx.x;
    const int bx   = blockIdx.x;
    const int w    = tid >> 5;
    const int lane = tid & 31;
    const uint32_t sb = smem_u32(dyn);
    const int srcq = tid & 63;

    if (bx < LNCTA) {
        // =================== LSTM role ===================
        float* gates = (float*)(dyn + OFF_GT);
        __half* hbuf = (__half*)(dyn + OFF_HB);
        const uint32_t aWH = sb + OFF_WH;
        const uint32_t aAH = sb + OFF_AH;

        // load W_hh slice fp32 -> fp16 (round) -> smem (one-time)
        {
            const float4* ws = (const float4*)Whh;
#pragma unroll 4
            for (int it = 0; it < 16; ++it) {
                int idx = tid + it * 256;
                int r = idx >> 7, qf = idx & 127;
                int gr = (r >> 3) * 512 + bx * 8 + (r & 7);
                float4 v = ws[(size_t)gr * 128 + qf];
                __half2 h0 = __floats2half2_rn(v.x, v.y);
                __half2 h1 = __floats2half2_rn(v.z, v.w);
                *(uint2*)(dyn + OFF_WH + (r * LTS + qf * 4) * 2)
                    = make_uint2(h2u(h0), h2u(h1));
            }
        }

        const int mt = w & 1;
        const int nt = w >> 1;
        const int rowA  = mt * 16 + (lane & 15);
        const int colA8 = (lane >> 4) << 3;
        const int rowB  = nt * 8 + (lane & 7);
        const int colB8 = (lane >> 3) << 3;
        const int gq = lane >> 2, tq = lane & 3;

        float c_state = 0.f;
        const int jh = bx * 8 + w;
        __syncthreads();

        // ---- hoist W_hh fragments into registers (loop-invariant) ----
        uint32_t bW[16][4];
#pragma unroll
        for (int kb = 0; kb < 16; ++kb)
            ldsm4(bW[kb][0], bW[kb][1], bW[kb][2], bW[kb][3],
                  aWH + (rowB * LTS + kb * 32 + colB8) * 2);

        for (int t = 0; t < 64; ++t) {
            float gpre[4];
#pragma unroll
            for (int g = 0; g < 4; ++g)
                gpre[g] = __ldcg(&g_Gin[(size_t)t * (G_ * B_)
                                        + (size_t)(g * 512 + jh) * B_ + lane]);

            if (t > 0) {
                // ---- dataflow staging: wait on my producer, stage its slice ----
                wait_flag(srcq, (unsigned)t);
                const uint4* hh = (const uint4*)(g_hsb + (size_t)(t - 1) * B_ * H_);
#pragma unroll
                for (int it = 0; it < 8; ++it) {
                    int idx = tid + it * 256;          // = b*64 + srcq
                    int b = idx >> 6;
                    cpa16(aAH + (b * LTS + srcq * 8) * 2, hh + idx);
                }
                CP_COMMIT();
                CP_WAIT(0);
                __syncthreads();

                // ---- gates = h @ W_hi^T : 1 pass, W frags in registers ----
                float d0[4] = {0, 0, 0, 0};
#pragma unroll
                for (int kb = 0; kb < 16; ++kb) {
                    uint32_t aH0[4], aH1[4];
                    ldsm4(aH0[0],aH0[1],aH0[2],aH0[3], aAH + (rowA*LTS + kb*32      + colA8)*2);
                    ldsm4(aH1[0],aH1[1],aH1[2],aH1[3], aAH + (rowA*LTS + kb*32 + 16 + colA8)*2);
                    mma_f16(d0, aH0, bW[kb] + 0);
                    mma_f16(d0, aH1, bW[kb] + 2);
                }
                {
                    int r0 = mt * 16 + gq;
                    int cc = nt * 8 + tq * 2;
                    gates[r0 * 33 + cc]           = d0[0];
                    gates[r0 * 33 + cc + 1]       = d0[1];
                    gates[(r0 + 8) * 33 + cc]     = d0[2];
                    gates[(r0 + 8) * 33 + cc + 1] = d0[3];
                }
            }
            __syncthreads();

            {
                const int b = lane;
                float gv[4];
#pragma unroll
                for (int g = 0; g < 4; ++g) {
                    float s = gpre[g];
                    if (t > 0) s += gates[b * 33 + g * 8 + w];
                    gv[g] = s;
                }
                float i_ = sigmoidf_(gv[0]);
                float f_ = sigmoidf_(gv[1]);
                float gg = tanhf(gv[2]);
                float o_ = sigmoidf_(gv[3]);
                c_state = f_ * c_state + i_ * gg;
                float h = o_ * tanhf(c_state);
                hbuf[b * 8 + w] = __float2half(h);     // smem bounce
            }
            __syncthreads();

            // ---- coalesced publish: warp 0 stores 32 x 16B rows, then
            //      releases (both in warp 0 -> warp-local ordering suffices) ----
            if (tid < 32) {
                *(uint4*)(g_hsb + (size_t)t * B_ * H_ + tid * 512 + bx * 8)
                    = *(const uint4*)(hbuf + tid * 8);
                __syncwarp();
                if (tid == 0) st_rel(&g_flags[bx * 32], (unsigned)(t + 1));
            }
        }
    } else {
        // =================== FC worker role ===================
        const int j = bx - LNCTA;            // 0..78
        const int n0 = j * 128;
        float* bias_s = (float*)(dyn + OFF_FBS);
        const uint32_t aFB = sb + OFF_FB;
        const uint32_t aAH = sb + OFF_FAH;

        // load fc_W tile fp32 -> fp16 -> smem (one-time, hidden behind step 0)
        {
            const float4* fw = (const float4*)fcW;
#pragma unroll 8
            for (int it = 0; it < 64; ++it) {
                int idx = tid + it * 256;
                int r = idx >> 7, qf = idx & 127;
                int n = n0 + r;
                float4 v = (n < V_) ? fw[(size_t)n * 128 + qf]
                                    : make_float4(0.f, 0.f, 0.f, 0.f);
                __half2 h0 = __floats2half2_rn(v.x, v.y);
                __half2 h1 = __floats2half2_rn(v.z, v.w);
                *(uint2*)(dyn + OFF_FB + (r * FTS + qf * 4) * 2)
                    = make_uint2(h2u(h0), h2u(h1));
            }
        }
        for (int i = tid; i < 128; i += 256) {
            int n = n0 + i;
            bias_s[i] = (n < V_) ? fc_b[n] : 0.f;
        }
        __syncthreads();

        const int rowA  = lane & 15;
        const int colA8 = (lane >> 4) << 3;
        const int g2    = lane >> 3;
        const int rowB  = w * 16 + ((g2 & 2) << 2) + (lane & 7);
        const int colB8 = (g2 & 1) << 3;
        const int gq = lane >> 2, tq = lane & 3;

        for (int t = 0; t < 64; ++t) {
            wait_flag(srcq, (unsigned)(t + 1));
            {
                const uint4* hh = (const uint4*)(g_hsb + (size_t)t * B_ * H_);
#pragma unroll
                for (int it = 0; it < 8; ++it) {
                    int idx = tid + it * 256;
                    int b = idx >> 6;
                    cpa16(aAH + (b * FTS + srcq * 8) * 2, hh + idx);
                }
                CP_COMMIT();
                CP_WAIT(0);
                __syncthreads();
            }

            float d[2][2][4];
#pragma unroll
            for (int i = 0; i < 2; i++)
#pragma unroll
                for (int jn = 0; jn < 2; jn++)
#pragma unroll
                    for (int q = 0; q < 4; q++) d[i][jn][q] = 0.f;
#pragma unroll
            for (int kb = 0; kb < 32; ++kb) {
                uint32_t aH[2][4], b[2][2];
                ldsm4(aH[0][0],aH[0][1],aH[0][2],aH[0][3], aAH + ((rowA     )*FTS + kb*16 + colA8)*2);
                ldsm4(aH[1][0],aH[1][1],aH[1][2],aH[1][3], aAH + ((rowA + 16)*FTS + kb*16 + colA8)*2);
                ldsm4(b[0][0], b[0][1], b[1][0], b[1][1],  aFB + (rowB*FTS + kb*16 + colB8)*2);
#pragma unroll
                for (int mb = 0; mb < 2; ++mb)
#pragma unroll
                    for (int nb = 0; nb < 2; ++nb)
                        mma_f16(d[mb][nb], aH[mb], b[nb]);
            }

#pragma unroll
            for (int mb = 0; mb < 2; ++mb) {
#pragma unroll
                for (int half = 0; half < 2; ++half) {
                    int b = mb * 16 + gq + half * 8;
                    float* crow = out + (size_t)b * (T_ * V_) + (size_t)t * V_;
#pragma unroll
                    for (int nb = 0; nb < 2; ++nb) {
                        int nl = w * 16 + nb * 8 + tq * 2;
                        int n  = n0 + nl;
                        if (n < V_) {
                            float2 o;
                            o.x = d[mb][nb][half * 2 + 0] + bias_s[nl];
                            o.y = d[mb][nb][half * 2 + 1] + bias_s[nl + 1];
                            *(float2*)&crow[n] = o;
                        }
                    }
                }
            }
            __syncthreads();
        }
    }
}

// ------------------------- launch ------------------------------------------
extern "C" void kernel_launch(void* const* d_in, const int* in_sizes, int n_in,
                              void* d_out, int out_size)
{
    const float* features = (const float*)d_in[0];
    const int*   captions = (const int*)d_in[1];
    // d_in[2] = forward_approach (unused)
    const float* embed = (const float*)d_in[3];
    const float* W_ih  = (const float*)d_in[4];
    const float* W_hh  = (const float*)d_in[5];
    const float* b_ih  = (const float*)d_in[6];
    const float* b_hh  = (const float*)d_in[7];
    const float* fc_W  = (const float*)d_in[8];
    const float* fc_b  = (const float*)d_in[9];
    float* out = (float*)d_out;

    float *pGin, *pbias;
    __half *pXh, *pWih_h;
    cudaGetSymbolAddress((void**)&pGin,   g_Gin);
    cudaGetSymbolAddress((void**)&pbias,  g_biasg);
    cudaGetSymbolAddress((void**)&pXh,    g_Xh);
    cudaGetSymbolAddress((void**)&pWih_h, g_Wih_h);

    const int SMEM_G1 = 2 * 2 * TILE_B + 512;    // 41472
    cudaFuncSetAttribute(gin_gemm, cudaFuncAttributeMaxDynamicSharedMemorySize, SMEM_G1);
    cudaFuncSetAttribute(fused_lstm_fc, cudaFuncAttributeMaxDynamicSharedMemorySize, FUSED_SMEM);

    // 1) merged prep: X fp16 + W_ih fp16 + fused bias + flag reset (one launch)
    prep_kernel<<<2048, 256>>>(
        (const float4*)features, captions, (const float4*)embed,
        (const float4*)W_ih, (const float4*)b_ih, (const float4*)b_hh);

    // 2) Gin[t][n][b] = Xh @ Wih_h^T + (b_ih + b_hh)   (fp16 1-pass)
    gin_gemm<<<dim3(G_ / 128, (T_ * B_) / 128), 256, SMEM_G1>>>(
        pXh, pWih_h, pbias, pGin);

    // 3) fused persistent LSTM + FC (W-frag hoist, warp-local publish tail)
    fused_lstm_fc<<<LNCTA + FNCTA, 256, FUSED_SMEM>>>(W_hh, fc_W, fc_b, out);
}